// round 1
// baseline (speedup 1.0000x reference)
#include <cuda_runtime.h>
#include <math.h>

#define L_SEQ 2048
#define NB    2
#define EMB   1024
#define NHEAD 16
#define HDIM  64
#define ROWS  (L_SEQ * NB)   /* 4096 */
#define FFN   (4 * EMB)      /* 4096 */
#define QSCALE (1.0f / 64.0f)

// ---------------- scratch (no allocation allowed; __device__ globals) ----------
__device__ float g_y[(size_t)ROWS * EMB];        // LN output (reused for LN1 and LN2)
__device__ float g_qkv[(size_t)ROWS * 3 * EMB];  // QKV
__device__ float g_o[(size_t)ROWS * EMB];        // attention output
__device__ float g_x1[(size_t)ROWS * EMB];       // x + attn_out
__device__ float g_h[(size_t)ROWS * FFN];        // GELU(fc) output

// ---------------- LayerNorm: one block per row, 256 threads, float4 -----------
__global__ void ln_kernel(const float* __restrict__ x,
                          const float* __restrict__ w,
                          const float* __restrict__ b,
                          float* __restrict__ y) {
    int row = blockIdx.x;
    int t = threadIdx.x;                      // 256 threads * 4 = 1024
    const float4 v = ((const float4*)(x + (size_t)row * EMB))[t];
    float s  = v.x + v.y + v.z + v.w;
    float sq = v.x * v.x + v.y * v.y + v.z * v.z + v.w * v.w;
    #pragma unroll
    for (int o = 16; o; o >>= 1) {
        s  += __shfl_xor_sync(0xffffffffu, s, o);
        sq += __shfl_xor_sync(0xffffffffu, sq, o);
    }
    __shared__ float ss[8], ssq[8];
    int wid = t >> 5, lid = t & 31;
    if (lid == 0) { ss[wid] = s; ssq[wid] = sq; }
    __syncthreads();
    if (t == 0) {
        float a = 0.f, c = 0.f;
        #pragma unroll
        for (int i = 0; i < 8; i++) { a += ss[i]; c += ssq[i]; }
        ss[0] = a; ssq[0] = c;
    }
    __syncthreads();
    float mu  = ss[0] * (1.0f / EMB);
    float var = ssq[0] * (1.0f / EMB) - mu * mu;
    float rs  = rsqrtf(var + 1e-5f);
    const float4 wv = ((const float4*)w)[t];
    const float4 bv = ((const float4*)b)[t];
    float4 o;
    o.x = (v.x - mu) * rs * wv.x + bv.x;
    o.y = (v.y - mu) * rs * wv.y + bv.y;
    o.z = (v.z - mu) * rs * wv.z + bv.z;
    o.w = (v.w - mu) * rs * wv.w + bv.w;
    ((float4*)(y + (size_t)row * EMB))[t] = o;
}

// ---------------- GEMM: C[M,Nn] = A[M,K] * B[Nn,K]^T (+bias)(+GELU)(+res) ------
// BM=128, BN=64, BK=16, 256 threads, per-thread 8x4 micro-tile.
template <int ACT>
__global__ __launch_bounds__(256) void gemm_kernel(
    const float* __restrict__ A, const float* __restrict__ B,
    const float* __restrict__ bias, const float* __restrict__ res,
    float* __restrict__ C, int M, int Nn, int K) {
    const int BM = 128, BN = 64, BK = 16;
    __shared__ float As[BK][BM + 4];   // 132 floats/row -> 528B (16B-aligned)
    __shared__ float Bs[BK][BN + 4];   // 68 floats/row  -> 272B (16B-aligned)
    int t = threadIdx.x;
    int m0 = blockIdx.y * BM;
    int n0 = blockIdx.x * BN;
    int tx = t & 15;    // -> n
    int ty = t >> 4;    // -> m
    float acc[8][4] = {};
    const float* Ab = A + (size_t)m0 * K;
    const float* Bb = B + (size_t)n0 * K;

    for (int k0 = 0; k0 < K; k0 += BK) {
        // A tile: 128x16 = 512 float4, 2 per thread, transposed into As[k][m]
        #pragma unroll
        for (int i = 0; i < 2; i++) {
            int idx = t + i * 256;       // 0..511
            int row = idx >> 2;          // 0..127
            int c4  = idx & 3;           // 0..3
            float4 v = *(const float4*)(Ab + (size_t)row * K + k0 + c4 * 4);
            As[c4 * 4 + 0][row] = v.x;
            As[c4 * 4 + 1][row] = v.y;
            As[c4 * 4 + 2][row] = v.z;
            As[c4 * 4 + 3][row] = v.w;
        }
        // B tile: 64x16 = 256 float4, 1 per thread
        {
            int row = t >> 2;            // 0..63
            int c4  = t & 3;
            float4 v = *(const float4*)(Bb + (size_t)row * K + k0 + c4 * 4);
            Bs[c4 * 4 + 0][row] = v.x;
            Bs[c4 * 4 + 1][row] = v.y;
            Bs[c4 * 4 + 2][row] = v.z;
            Bs[c4 * 4 + 3][row] = v.w;
        }
        __syncthreads();
        #pragma unroll
        for (int kk = 0; kk < BK; kk++) {
            float4 a0 = *(const float4*)&As[kk][ty * 8];
            float4 a1 = *(const float4*)&As[kk][ty * 8 + 4];
            float4 bf = *(const float4*)&Bs[kk][tx * 4];
            float am[8] = {a0.x, a0.y, a0.z, a0.w, a1.x, a1.y, a1.z, a1.w};
            float bn[4] = {bf.x, bf.y, bf.z, bf.w};
            #pragma unroll
            for (int i = 0; i < 8; i++)
                #pragma unroll
                for (int j = 0; j < 4; j++)
                    acc[i][j] += am[i] * bn[j];
        }
        __syncthreads();
    }

    float4 bv = *(const float4*)(bias + n0 + tx * 4);
    float bb[4] = {bv.x, bv.y, bv.z, bv.w};
    #pragma unroll
    for (int i = 0; i < 8; i++) {
        int row = m0 + ty * 8 + i;
        float vals[4];
        #pragma unroll
        for (int j = 0; j < 4; j++) {
            float v = acc[i][j] + bb[j];
            if (ACT == 1) v = 0.5f * v * (1.0f + erff(v * 0.70710678118f));  // exact GELU
            vals[j] = v;
        }
        if (res != nullptr) {
            float4 r = *(const float4*)(res + (size_t)row * Nn + n0 + tx * 4);
            vals[0] += r.x; vals[1] += r.y; vals[2] += r.z; vals[3] += r.w;
        }
        float4 o = {vals[0], vals[1], vals[2], vals[3]};
        *(float4*)(C + (size_t)row * Nn + n0 + tx * 4) = o;
    }
}

// ---------------- Flash attention, fp32 ----------------------------------------
// grid: (L/32 q-tiles, NB*NHEAD heads). block: 256 threads.
// Per block: 32 queries. Key tiles of 32. Online softmax; (m,l) in registers
// replicated across the 8 lanes owning each query row (warp-contiguous group).
__global__ __launch_bounds__(256) void attn_kernel(
    const float* __restrict__ qkv, float* __restrict__ out) {
    __shared__ float qs[32][65];
    __shared__ float ks[32][65];
    __shared__ float vs[32][68];   // 68 floats/row = 272B, float4-aligned
    __shared__ float ps[32][33];

    int t  = threadIdx.x;
    int bh = blockIdx.y;
    int n  = bh >> 4;
    int h  = bh & 15;
    int q0 = blockIdx.x * 32;
    int hcol = h * HDIM;

    // load + scale Q tile (32 x 64)
    #pragma unroll
    for (int i = 0; i < 2; i++) {
        int idx = t + i * 256;               // 0..511
        int qi = idx >> 4;
        int dq = (idx & 15) * 4;
        int l  = q0 + qi;
        float4 v = *(const float4*)(qkv + (size_t)(l * NB + n) * (3 * EMB) + hcol + dq);
        qs[qi][dq + 0] = v.x * QSCALE;
        qs[qi][dq + 1] = v.y * QSCALE;
        qs[qi][dq + 2] = v.z * QSCALE;
        qs[qi][dq + 3] = v.w * QSCALE;
    }
    __syncthreads();

    // ownership for softmax/PV: lane group of 8 per query row (warp-contiguous)
    int qi_a = t >> 3;        // 0..31
    int jg   = t & 7;         // 0..7
    int d0   = jg * 8;        // this thread owns output dims [d0, d0+8)
    // ownership for score phase: 2x2 micro-tile
    int tq = t >> 4, tk = t & 15;
    int qa = tq * 2, ka = tk * 2;

    float acc[8] = {0, 0, 0, 0, 0, 0, 0, 0};
    float m_run = -INFINITY;
    float l_run = 0.0f;

    for (int kt = 0; kt < L_SEQ / 32; kt++) {
        int k0 = kt * 32;
        // load K and V tiles (32 x 64 each)
        #pragma unroll
        for (int i = 0; i < 2; i++) {
            int idx = t + i * 256;
            int kj = idx >> 4;
            int dk = (idx & 15) * 4;
            int l  = k0 + kj;
            size_t base = (size_t)(l * NB + n) * (3 * EMB) + hcol + dk;
            float4 kv = *(const float4*)(qkv + base + EMB);
            float4 vv = *(const float4*)(qkv + base + 2 * EMB);
            ks[kj][dk + 0] = kv.x; ks[kj][dk + 1] = kv.y;
            ks[kj][dk + 2] = kv.z; ks[kj][dk + 3] = kv.w;
            vs[kj][dk + 0] = vv.x; vs[kj][dk + 1] = vv.y;
            vs[kj][dk + 2] = vv.z; vs[kj][dk + 3] = vv.w;
        }
        __syncthreads();

        // scores: 2x2 register blocking, 64-d dot from SMEM
        float s00 = 0.f, s01 = 0.f, s10 = 0.f, s11 = 0.f;
        #pragma unroll 8
        for (int d = 0; d < HDIM; d++) {
            float qav = qs[qa][d],     qbv = qs[qa + 1][d];
            float kav = ks[ka][d],     kbv = ks[ka + 1][d];
            s00 += qav * kav; s01 += qav * kbv;
            s10 += qbv * kav; s11 += qbv * kbv;
        }
        ps[qa][ka] = s00;     ps[qa][ka + 1] = s01;
        ps[qa + 1][ka] = s10; ps[qa + 1][ka + 1] = s11;
        __syncwarp();

        // online softmax: row stats across the 8-lane group
        float x0 = ps[qi_a][jg],      x1 = ps[qi_a][jg + 8];
        float x2 = ps[qi_a][jg + 16], x3 = ps[qi_a][jg + 24];
        float tmax = fmaxf(fmaxf(x0, x1), fmaxf(x2, x3));
        tmax = fmaxf(tmax, __shfl_xor_sync(0xffffffffu, tmax, 1));
        tmax = fmaxf(tmax, __shfl_xor_sync(0xffffffffu, tmax, 2));
        tmax = fmaxf(tmax, __shfl_xor_sync(0xffffffffu, tmax, 4));
        float m_new = fmaxf(m_run, tmax);
        float p0 = __expf(x0 - m_new), p1 = __expf(x1 - m_new);
        float p2 = __expf(x2 - m_new), p3 = __expf(x3 - m_new);
        float psum = p0 + p1 + p2 + p3;
        psum += __shfl_xor_sync(0xffffffffu, psum, 1);
        psum += __shfl_xor_sync(0xffffffffu, psum, 2);
        psum += __shfl_xor_sync(0xffffffffu, psum, 4);
        float corr = __expf(m_run - m_new);   // exp(-inf)=0 on first tile
        m_run = m_new;
        l_run = l_run * corr + psum;
        ps[qi_a][jg]      = p0; ps[qi_a][jg + 8]  = p1;
        ps[qi_a][jg + 16] = p2; ps[qi_a][jg + 24] = p3;
        #pragma unroll
        for (int dd = 0; dd < 8; dd++) acc[dd] *= corr;
        __syncwarp();

        // PV: acc[d0..d0+8) += sum_kj p[qi][kj] * V[kj][d]
        #pragma unroll 4
        for (int kj = 0; kj < 32; kj++) {
            float p = ps[qi_a][kj];
            float4 v0 = *(const float4*)&vs[kj][d0];
            float4 v1 = *(const float4*)&vs[kj][d0 + 4];
            acc[0] += p * v0.x; acc[1] += p * v0.y;
            acc[2] += p * v0.z; acc[3] += p * v0.w;
            acc[4] += p * v1.x; acc[5] += p * v1.y;
            acc[6] += p * v1.z; acc[7] += p * v1.w;
        }
        __syncthreads();   // before next tile overwrites ks/vs/ps
    }

    float inv = 1.0f / l_run;
    int l = q0 + qi_a;
    float* optr = out + (size_t)(l * NB + n) * EMB + hcol + d0;
    float4 o0 = {acc[0] * inv, acc[1] * inv, acc[2] * inv, acc[3] * inv};
    float4 o1 = {acc[4] * inv, acc[5] * inv, acc[6] * inv, acc[7] * inv};
    *(float4*)(optr)     = o0;
    *(float4*)(optr + 4) = o1;
}

// ---------------- driver --------------------------------------------------------
extern "C" void kernel_launch(void* const* d_in, const int* in_sizes, int n_in,
                              void* d_out, int out_size) {
    const float* x         = (const float*)d_in[0];
    const float* ln1_w     = (const float*)d_in[1];
    const float* ln1_b     = (const float*)d_in[2];
    const float* in_proj_w = (const float*)d_in[3];
    const float* in_proj_b = (const float*)d_in[4];
    const float* out_w     = (const float*)d_in[5];
    const float* out_b     = (const float*)d_in[6];
    const float* ln2_w     = (const float*)d_in[7];
    const float* ln2_b     = (const float*)d_in[8];
    const float* fc_w      = (const float*)d_in[9];
    const float* fc_b      = (const float*)d_in[10];
    const float* proj_w    = (const float*)d_in[11];
    const float* proj_b    = (const float*)d_in[12];
    float* out = (float*)d_out;

    float *y, *qkv, *o, *x1, *hbuf;
    cudaGetSymbolAddress((void**)&y,    g_y);
    cudaGetSymbolAddress((void**)&qkv,  g_qkv);
    cudaGetSymbolAddress((void**)&o,    g_o);
    cudaGetSymbolAddress((void**)&x1,   g_x1);
    cudaGetSymbolAddress((void**)&hbuf, g_h);

    // 1. y = LN1(x)
    ln_kernel<<<ROWS, 256>>>(x, ln1_w, ln1_b, y);
    // 2. qkv = y @ in_proj_w^T + in_proj_b
    gemm_kernel<0><<<dim3(3 * EMB / 64, ROWS / 128), 256>>>(
        y, in_proj_w, in_proj_b, nullptr, qkv, ROWS, 3 * EMB, EMB);
    // 3. o = attention(qkv)
    attn_kernel<<<dim3(L_SEQ / 32, NB * NHEAD), 256>>>(qkv, o);
    // 4. x1 = x + o @ out_w^T + out_b
    gemm_kernel<0><<<dim3(EMB / 64, ROWS / 128), 256>>>(
        o, out_w, out_b, x, x1, ROWS, EMB, EMB);
    // 5. y = LN2(x1)
    ln_kernel<<<ROWS, 256>>>(x1, ln2_w, ln2_b, y);
    // 6. h = GELU(y @ fc_w^T + fc_b)
    gemm_kernel<1><<<dim3(FFN / 64, ROWS / 128), 256>>>(
        y, fc_w, fc_b, nullptr, hbuf, ROWS, FFN, EMB);
    // 7. out = x1 + h @ proj_w^T + proj_b
    gemm_kernel<0><<<dim3(EMB / 64, ROWS / 128), 256>>>(
        hbuf, proj_w, proj_b, x1, out, ROWS, EMB, FFN);
}

// round 3
// speedup vs baseline: 2.3862x; 2.3862x over previous
#include <cuda_runtime.h>
#include <math.h>
#include <stdint.h>

#define L_SEQ 2048
#define NB    2
#define EMB   1024
#define NHEAD 16
#define HDIM  64
#define ROWS  (L_SEQ * NB)   /* 4096 */
#define FFN   (4 * EMB)      /* 4096 */
#define QSCALE (1.0f / 64.0f)

// ---------------- scratch (no allocation allowed; __device__ globals) ----------
__device__ float g_y[(size_t)ROWS * EMB];
__device__ float g_qkv[(size_t)ROWS * 3 * EMB];
__device__ float g_o[(size_t)ROWS * EMB];
__device__ float g_x1[(size_t)ROWS * EMB];
__device__ float g_h[(size_t)ROWS * FFN];

// ---------------- helpers -------------------------------------------------------
__device__ __forceinline__ uint32_t smem_u32(const void* p) {
    uint32_t a;
    asm("{ .reg .u64 t; cvta.to.shared.u64 t, %1; cvt.u32.u64 %0, t; }" : "=r"(a) : "l"(p));
    return a;
}
__device__ __forceinline__ void cp16(uint32_t s, const void* g) {
    asm volatile("cp.async.cg.shared.global [%0], [%1], 16;" :: "r"(s), "l"(g) : "memory");
}
#define CP_COMMIT() asm volatile("cp.async.commit_group;" ::: "memory")

__device__ __forceinline__ uint32_t f2tf(float f) {
    uint32_t u; asm("cvt.rna.tf32.f32 %0, %1;" : "=r"(u) : "f"(f)); return u;
}
__device__ __forceinline__ void mma_tf32(float* d, const uint32_t* a, const uint32_t* b) {
    asm volatile(
        "mma.sync.aligned.m16n8k8.row.col.f32.tf32.tf32.f32 "
        "{%0,%1,%2,%3}, {%4,%5,%6,%7}, {%8,%9}, {%0,%1,%2,%3};"
        : "+f"(d[0]), "+f"(d[1]), "+f"(d[2]), "+f"(d[3])
        : "r"(a[0]), "r"(a[1]), "r"(a[2]), "r"(a[3]), "r"(b[0]), "r"(b[1]));
}

// fast exp: FFMA-only, rel err ~1e-7
__device__ __forceinline__ float fexp(float x) {
    x = fmaxf(x, -80.0f);
    float t = x * 1.4426950408889634f;
    float r = t + 12582912.0f;
    float i = r - 12582912.0f;
    float f = t - i;
    float p = 1.3333558146428443e-3f;
    p = fmaf(p, f, 9.6181291076284772e-3f);
    p = fmaf(p, f, 5.5504108664821580e-2f);
    p = fmaf(p, f, 2.4022650695910072e-1f);
    p = fmaf(p, f, 6.9314718055994531e-1f);
    p = fmaf(p, f, 1.0f);
    return p * __int_as_float(((int)i + 127) << 23);
}

// ---------------- LayerNorm -----------------------------------------------------
__global__ void ln_kernel(const float* __restrict__ x,
                          const float* __restrict__ w,
                          const float* __restrict__ b,
                          float* __restrict__ y) {
    int row = blockIdx.x;
    int t = threadIdx.x;
    const float4 v = ((const float4*)(x + (size_t)row * EMB))[t];
    float s  = v.x + v.y + v.z + v.w;
    float sq = v.x * v.x + v.y * v.y + v.z * v.z + v.w * v.w;
    #pragma unroll
    for (int o = 16; o; o >>= 1) {
        s  += __shfl_xor_sync(0xffffffffu, s, o);
        sq += __shfl_xor_sync(0xffffffffu, sq, o);
    }
    __shared__ float ss[8], ssq[8];
    int wid = t >> 5, lid = t & 31;
    if (lid == 0) { ss[wid] = s; ssq[wid] = sq; }
    __syncthreads();
    if (t == 0) {
        float a = 0.f, c = 0.f;
        #pragma unroll
        for (int i = 0; i < 8; i++) { a += ss[i]; c += ssq[i]; }
        ss[0] = a; ssq[0] = c;
    }
    __syncthreads();
    float mu  = ss[0] * (1.0f / EMB);
    float var = ssq[0] * (1.0f / EMB) - mu * mu;
    float rs  = rsqrtf(var + 1e-5f);
    const float4 wv = ((const float4*)w)[t];
    const float4 bv = ((const float4*)b)[t];
    float4 o;
    o.x = (v.x - mu) * rs * wv.x + bv.x;
    o.y = (v.y - mu) * rs * wv.y + bv.y;
    o.z = (v.z - mu) * rs * wv.z + bv.z;
    o.w = (v.w - mu) * rs * wv.w + bv.w;
    ((float4*)(y + (size_t)row * EMB))[t] = o;
}

// ---------------- tf32 mma.sync GEMM: C[M,Nn] = A[M,K]*B[Nn,K]^T ----------------
// Block 128x256, BK=32, 8 warps in 2x4, warp tile 64x64 (4x8 m16n8k8 frags).
#define GBM 128
#define GBN 256
#define GBK 32
#define GPITCH 36                                   /* floats; bank = 4*row+col */
#define A_STAGE_F (GBM * GPITCH)                    /* 4608 floats */
#define B_STAGE_F (GBN * GPITCH)                    /* 9216 floats */
#define STAGE_F   (A_STAGE_F + B_STAGE_F)           /* 13824 floats */
#define G_SMEM_BYTES (2 * STAGE_F * 4)              /* 110592 bytes */

template <int ACT>
__global__ __launch_bounds__(256, 1)
void gemm_tc(const float* __restrict__ A, const float* __restrict__ B,
             const float* __restrict__ bias, const float* __restrict__ res,
             float* __restrict__ C, int M, int Nn, int K) {
    extern __shared__ float sm[];
    uint32_t smemBase = smem_u32(sm);
    int t = threadIdx.x;
    int w = t >> 5, lane = t & 31;
    int g = lane >> 2, c = lane & 3;
    int wm = w & 1, wn = w >> 1;
    int m0 = blockIdx.y * GBM;
    int n0 = blockIdx.x * GBN;
    int KT = K / GBK;

    const float* Ab = A + (size_t)m0 * K;
    const float* Bb = B + (size_t)n0 * K;

    float d[4][8][4];
    #pragma unroll
    for (int i = 0; i < 4; i++)
        #pragma unroll
        for (int j = 0; j < 8; j++)
            #pragma unroll
            for (int q = 0; q < 4; q++) d[i][j][q] = 0.f;

    // ---- async tile loader ----
    auto load_stage = [&](int s, int k0) {
        uint32_t aS = smemBase + (uint32_t)(s * STAGE_F * 4);
        uint32_t bS = aS + A_STAGE_F * 4;
        #pragma unroll
        for (int i = 0; i < 4; i++) {
            int ch = t + i * 256;            // 0..1023
            int row = ch >> 3, cc = ch & 7;
            cp16(aS + (uint32_t)(row * GPITCH + cc * 4) * 4,
                 Ab + (size_t)row * K + k0 + cc * 4);
        }
        #pragma unroll
        for (int i = 0; i < 8; i++) {
            int ch = t + i * 256;            // 0..2047
            int row = ch >> 3, cc = ch & 7;
            cp16(bS + (uint32_t)(row * GPITCH + cc * 4) * 4,
                 Bb + (size_t)row * K + k0 + cc * 4);
        }
    };

    load_stage(0, 0);
    CP_COMMIT();

    for (int kt = 0; kt < KT; kt++) {
        if (kt + 1 < KT) {
            load_stage((kt + 1) & 1, (kt + 1) * GBK);
            CP_COMMIT();
            asm volatile("cp.async.wait_group 1;" ::: "memory");
        } else {
            asm volatile("cp.async.wait_group 0;" ::: "memory");
        }
        __syncthreads();

        const float* As = sm + (kt & 1) * STAGE_F;
        const float* Bs = As + A_STAGE_F;

        #pragma unroll
        for (int kk = 0; kk < GBK / 8; kk++) {
            int kc = kk * 8;
            uint32_t a[4][4], b[8][2];
            #pragma unroll
            for (int i = 0; i < 4; i++) {
                int r = wm * 64 + i * 16 + g;
                const float* p0 = As + r * GPITCH + kc + c;
                const float* p1 = As + (r + 8) * GPITCH + kc + c;
                a[i][0] = f2tf(p0[0]);
                a[i][1] = f2tf(p1[0]);
                a[i][2] = f2tf(p0[4]);
                a[i][3] = f2tf(p1[4]);
            }
            #pragma unroll
            for (int j = 0; j < 8; j++) {
                int n = wn * 64 + j * 8 + g;
                const float* p = Bs + n * GPITCH + kc + c;
                b[j][0] = f2tf(p[0]);
                b[j][1] = f2tf(p[4]);
            }
            #pragma unroll
            for (int i = 0; i < 4; i++)
                #pragma unroll
                for (int j = 0; j < 8; j++)
                    mma_tf32(d[i][j], a[i], b[j]);
        }
        __syncthreads();
    }

    // ---- epilogue ----
    #pragma unroll
    for (int i = 0; i < 4; i++) {
        int row0 = m0 + wm * 64 + i * 16 + g;
        #pragma unroll
        for (int j = 0; j < 8; j++) {
            int col = n0 + wn * 64 + j * 8 + 2 * c;
            float2 bv = *(const float2*)(bias + col);
            float v0 = d[i][j][0] + bv.x;
            float v1 = d[i][j][1] + bv.y;
            float v2 = d[i][j][2] + bv.x;
            float v3 = d[i][j][3] + bv.y;
            if (ACT == 1) {
                v0 = 0.5f * v0 * (1.0f + erff(v0 * 0.70710678118f));
                v1 = 0.5f * v1 * (1.0f + erff(v1 * 0.70710678118f));
                v2 = 0.5f * v2 * (1.0f + erff(v2 * 0.70710678118f));
                v3 = 0.5f * v3 * (1.0f + erff(v3 * 0.70710678118f));
            }
            if (res != nullptr) {
                float2 r0 = *(const float2*)(res + (size_t)row0 * Nn + col);
                float2 r1 = *(const float2*)(res + (size_t)(row0 + 8) * Nn + col);
                v0 += r0.x; v1 += r0.y; v2 += r1.x; v3 += r1.y;
            }
            float2 o0 = {v0, v1}, o1 = {v2, v3};
            *(float2*)(C + (size_t)row0 * Nn + col) = o0;
            *(float2*)(C + (size_t)(row0 + 8) * Nn + col) = o1;
        }
    }
}

// ---------------- Flash attention: 64x64 tiles, 4x4 micro, fast exp -------------
#define AQT 64
#define AKT 64
#define APITCH 68
#define ATT_SMEM_FLOATS (4 * AQT * APITCH + 3 * AQT)

__global__ __launch_bounds__(256) void attn_kernel(
    const float* __restrict__ qkv, float* __restrict__ out) {
    extern __shared__ float sm[];
    float* QS = sm;
    float* KS = QS + AQT * APITCH;
    float* VS = KS + AQT * APITCH;
    float* PS = VS + AQT * APITCH;
    float* MR = PS + AQT * APITCH;
    float* LR = MR + AQT;
    float* CR = LR + AQT;

    int t  = threadIdx.x;
    int bh = blockIdx.y;
    int n  = bh >> 4;
    int h  = bh & 15;
    int q0 = blockIdx.x * AQT;
    int hcol = h * HDIM;

    #pragma unroll
    for (int i = 0; i < 4; i++) {
        int idx = t + i * 256;
        int qi = idx >> 4;
        int c  = (idx & 15) * 4;
        float4 v = *(const float4*)(qkv + ((size_t)((q0 + qi) * NB + n)) * (3 * EMB) + hcol + c);
        float4 o = {v.x * QSCALE, v.y * QSCALE, v.z * QSCALE, v.w * QSCALE};
        *(float4*)&QS[qi * APITCH + c] = o;
    }
    if (t < AQT) { MR[t] = -1e30f; LR[t] = 0.0f; }
    __syncthreads();

    int tq = t >> 4, tk = t & 15;
    int qa = tq * 4, ka = tk * 4;
    int srow = t >> 2, sl = t & 3;

    float o00[4][4] = {};

    for (int kt = 0; kt < L_SEQ / AKT; kt++) {
        int k0 = kt * AKT;
        #pragma unroll
        for (int i = 0; i < 4; i++) {
            int idx = t + i * 256;
            int r = idx >> 4;
            int c = (idx & 15) * 4;
            size_t base = ((size_t)((k0 + r) * NB + n)) * (3 * EMB) + hcol + c;
            float4 kv = *(const float4*)(qkv + base + EMB);
            float4 vv = *(const float4*)(qkv + base + 2 * EMB);
            *(float4*)&KS[r * APITCH + c] = kv;
            *(float4*)&VS[r * APITCH + c] = vv;
        }
        __syncthreads();

        float s[4][4] = {};
        #pragma unroll
        for (int d4 = 0; d4 < 16; d4++) {
            float4 qv[4], kv[4];
            #pragma unroll
            for (int i = 0; i < 4; i++) qv[i] = *(const float4*)&QS[(qa + i) * APITCH + d4 * 4];
            #pragma unroll
            for (int j = 0; j < 4; j++) kv[j] = *(const float4*)&KS[(ka + j) * APITCH + d4 * 4];
            #pragma unroll
            for (int i = 0; i < 4; i++)
                #pragma unroll
                for (int j = 0; j < 4; j++)
                    s[i][j] += qv[i].x * kv[j].x + qv[i].y * kv[j].y
                             + qv[i].z * kv[j].z + qv[i].w * kv[j].w;
        }
        #pragma unroll
        for (int i = 0; i < 4; i++) {
            float4 o = {s[i][0], s[i][1], s[i][2], s[i][3]};
            *(float4*)&PS[(qa + i) * APITCH + ka] = o;
        }
        __syncthreads();

        {
            float xv[16];
            #pragma unroll
            for (int u = 0; u < 4; u++) {
                float4 v = *(const float4*)&PS[srow * APITCH + sl * 16 + u * 4];
                xv[u * 4 + 0] = v.x; xv[u * 4 + 1] = v.y;
                xv[u * 4 + 2] = v.z; xv[u * 4 + 3] = v.w;
            }
            float mx = xv[0];
            #pragma unroll
            for (int u = 1; u < 16; u++) mx = fmaxf(mx, xv[u]);
            mx = fmaxf(mx, __shfl_xor_sync(0xffffffffu, mx, 1));
            mx = fmaxf(mx, __shfl_xor_sync(0xffffffffu, mx, 2));
            float m_old = MR[srow];
            float m_new = fmaxf(m_old, mx);
            float sum = 0.f;
            #pragma unroll
            for (int u = 0; u < 16; u++) { xv[u] = fexp(xv[u] - m_new); sum += xv[u]; }
            #pragma unroll
            for (int u = 0; u < 4; u++) {
                float4 v = {xv[u * 4 + 0], xv[u * 4 + 1], xv[u * 4 + 2], xv[u * 4 + 3]};
                *(float4*)&PS[srow * APITCH + sl * 16 + u * 4] = v;
            }
            sum += __shfl_xor_sync(0xffffffffu, sum, 1);
            sum += __shfl_xor_sync(0xffffffffu, sum, 2);
            if (sl == 0) {
                float corr = fexp(m_old - m_new);
                CR[srow] = corr;
                LR[srow] = LR[srow] * corr + sum;
                MR[srow] = m_new;
            }
        }
        __syncthreads();

        {
            float c0 = CR[qa + 0], c1 = CR[qa + 1], c2 = CR[qa + 2], c3 = CR[qa + 3];
            #pragma unroll
            for (int j = 0; j < 4; j++) {
                o00[0][j] *= c0; o00[1][j] *= c1; o00[2][j] *= c2; o00[3][j] *= c3;
            }
            #pragma unroll 8
            for (int kj = 0; kj < AKT; kj++) {
                float p0 = PS[(qa + 0) * APITCH + kj];
                float p1 = PS[(qa + 1) * APITCH + kj];
                float p2 = PS[(qa + 2) * APITCH + kj];
                float p3 = PS[(qa + 3) * APITCH + kj];
                float4 v = *(const float4*)&VS[kj * APITCH + ka];
                o00[0][0] += p0 * v.x; o00[0][1] += p0 * v.y; o00[0][2] += p0 * v.z; o00[0][3] += p0 * v.w;
                o00[1][0] += p1 * v.x; o00[1][1] += p1 * v.y; o00[1][2] += p1 * v.z; o00[1][3] += p1 * v.w;
                o00[2][0] += p2 * v.x; o00[2][1] += p2 * v.y; o00[2][2] += p2 * v.z; o00[2][3] += p2 * v.w;
                o00[3][0] += p3 * v.x; o00[3][1] += p3 * v.y; o00[3][2] += p3 * v.z; o00[3][3] += p3 * v.w;
            }
        }
        __syncthreads();
    }

    #pragma unroll
    for (int i = 0; i < 4; i++) {
        float inv = 1.0f / LR[qa + i];
        float4 o = {o00[i][0] * inv, o00[i][1] * inv, o00[i][2] * inv, o00[i][3] * inv};
        *(float4*)(out + ((size_t)((q0 + qa + i) * NB + n)) * EMB + hcol + ka) = o;
    }
}

// ---------------- driver --------------------------------------------------------
extern "C" void kernel_launch(void* const* d_in, const int* in_sizes, int n_in,
                              void* d_out, int out_size) {
    const float* x         = (const float*)d_in[0];
    const float* ln1_w     = (const float*)d_in[1];
    const float* ln1_b     = (const float*)d_in[2];
    const float* in_proj_w = (const float*)d_in[3];
    const float* in_proj_b = (const float*)d_in[4];
    const float* out_w     = (const float*)d_in[5];
    const float* out_b     = (const float*)d_in[6];
    const float* ln2_w     = (const float*)d_in[7];
    const float* ln2_b     = (const float*)d_in[8];
    const float* fc_w      = (const float*)d_in[9];
    const float* fc_b      = (const float*)d_in[10];
    const float* proj_w    = (const float*)d_in[11];
    const float* proj_b    = (const float*)d_in[12];
    float* out = (float*)d_out;

    float *y, *qkv, *o, *x1, *hbuf;
    cudaGetSymbolAddress((void**)&y,    g_y);
    cudaGetSymbolAddress((void**)&qkv,  g_qkv);
    cudaGetSymbolAddress((void**)&o,    g_o);
    cudaGetSymbolAddress((void**)&x1,   g_x1);
    cudaGetSymbolAddress((void**)&hbuf, g_h);

    static bool attr_done = false;
    if (!attr_done) {
        cudaFuncSetAttribute(gemm_tc<0>, cudaFuncAttributeMaxDynamicSharedMemorySize, G_SMEM_BYTES);
        cudaFuncSetAttribute(gemm_tc<1>, cudaFuncAttributeMaxDynamicSharedMemorySize, G_SMEM_BYTES);
        cudaFuncSetAttribute(attn_kernel, cudaFuncAttributeMaxDynamicSharedMemorySize,
                             ATT_SMEM_FLOATS * (int)sizeof(float));
        attr_done = true;
    }

    // 1. y = LN1(x)
    ln_kernel<<<ROWS, 256>>>(x, ln1_w, ln1_b, y);
    // 2. qkv = y @ in_proj_w^T + in_proj_b
    gemm_tc<0><<<dim3(3 * EMB / GBN, ROWS / GBM), 256, G_SMEM_BYTES>>>(
        y, in_proj_w, in_proj_b, nullptr, qkv, ROWS, 3 * EMB, EMB);
    // 3. o = attention(qkv)
    attn_kernel<<<dim3(L_SEQ / AQT, NB * NHEAD), 256, ATT_SMEM_FLOATS * sizeof(float)>>>(qkv, o);
    // 4. x1 = x + o @ out_w^T + out_b
    gemm_tc<0><<<dim3(EMB / GBN, ROWS / GBM), 256, G_SMEM_BYTES>>>(
        o, out_w, out_b, x, x1, ROWS, EMB, EMB);
    // 5. y = LN2(x1)
    ln_kernel<<<ROWS, 256>>>(x1, ln2_w, ln2_b, y);
    // 6. h = GELU(y @ fc_w^T + fc_b)
    gemm_tc<1><<<dim3(FFN / GBN, ROWS / GBM), 256, G_SMEM_BYTES>>>(
        y, fc_w, fc_b, nullptr, hbuf, ROWS, FFN, EMB);
    // 7. out = x1 + h @ proj_w^T + proj_b
    gemm_tc<0><<<dim3(EMB / GBN, ROWS / GBM), 256, G_SMEM_BYTES>>>(
        hbuf, proj_w, proj_b, x1, out, ROWS, EMB, FFN);
}

// round 4
// speedup vs baseline: 4.9820x; 2.0878x over previous
#include <cuda_runtime.h>
#include <math.h>
#include <stdint.h>

#define L_SEQ 2048
#define NB    2
#define EMB   1024
#define NHEAD 16
#define HDIM  64
#define ROWS  (L_SEQ * NB)   /* 4096 */
#define FFN   (4 * EMB)      /* 4096 */
#define QSCALE (1.0f / 64.0f)

// ---------------- scratch (no allocation allowed; __device__ globals) ----------
__device__ float g_y[(size_t)ROWS * EMB];
__device__ float g_qkv[(size_t)ROWS * 3 * EMB];
__device__ float g_o[(size_t)ROWS * EMB];
__device__ float g_x1[(size_t)ROWS * EMB];
__device__ float g_h[(size_t)ROWS * FFN];

// ---------------- helpers -------------------------------------------------------
__device__ __forceinline__ uint32_t smem_u32(const void* p) {
    uint32_t a;
    asm("{ .reg .u64 t; cvta.to.shared.u64 t, %1; cvt.u32.u64 %0, t; }" : "=r"(a) : "l"(p));
    return a;
}
__device__ __forceinline__ void cp16(uint32_t s, const void* g) {
    asm volatile("cp.async.cg.shared.global [%0], [%1], 16;" :: "r"(s), "l"(g) : "memory");
}
#define CP_COMMIT() asm volatile("cp.async.commit_group;" ::: "memory")

__device__ __forceinline__ uint32_t f2tf(float f) {
    uint32_t u; asm("cvt.rna.tf32.f32 %0, %1;" : "=r"(u) : "f"(f)); return u;
}
__device__ __forceinline__ void mma_tf32(float* d, const uint32_t* a, const uint32_t* b) {
    asm volatile(
        "mma.sync.aligned.m16n8k8.row.col.f32.tf32.tf32.f32 "
        "{%0,%1,%2,%3}, {%4,%5,%6,%7}, {%8,%9}, {%0,%1,%2,%3};"
        : "+f"(d[0]), "+f"(d[1]), "+f"(d[2]), "+f"(d[3])
        : "r"(a[0]), "r"(a[1]), "r"(a[2]), "r"(a[3]), "r"(b[0]), "r"(b[1]));
}

// fast exp: FFMA-only, rel err ~1e-7
__device__ __forceinline__ float fexp(float x) {
    x = fmaxf(x, -80.0f);
    float t = x * 1.4426950408889634f;
    float r = t + 12582912.0f;
    float i = r - 12582912.0f;
    float f = t - i;
    float p = 1.3333558146428443e-3f;
    p = fmaf(p, f, 9.6181291076284772e-3f);
    p = fmaf(p, f, 5.5504108664821580e-2f);
    p = fmaf(p, f, 2.4022650695910072e-1f);
    p = fmaf(p, f, 6.9314718055994531e-1f);
    p = fmaf(p, f, 1.0f);
    return p * __int_as_float(((int)i + 127) << 23);
}

// ---------------- LayerNorm -----------------------------------------------------
__global__ void ln_kernel(const float* __restrict__ x,
                          const float* __restrict__ w,
                          const float* __restrict__ b,
                          float* __restrict__ y) {
    int row = blockIdx.x;
    int t = threadIdx.x;
    const float4 v = ((const float4*)(x + (size_t)row * EMB))[t];
    float s  = v.x + v.y + v.z + v.w;
    float sq = v.x * v.x + v.y * v.y + v.z * v.z + v.w * v.w;
    #pragma unroll
    for (int o = 16; o; o >>= 1) {
        s  += __shfl_xor_sync(0xffffffffu, s, o);
        sq += __shfl_xor_sync(0xffffffffu, sq, o);
    }
    __shared__ float ss[8], ssq[8];
    int wid = t >> 5, lid = t & 31;
    if (lid == 0) { ss[wid] = s; ssq[wid] = sq; }
    __syncthreads();
    if (t == 0) {
        float a = 0.f, c = 0.f;
        #pragma unroll
        for (int i = 0; i < 8; i++) { a += ss[i]; c += ssq[i]; }
        ss[0] = a; ssq[0] = c;
    }
    __syncthreads();
    float mu  = ss[0] * (1.0f / EMB);
    float var = ssq[0] * (1.0f / EMB) - mu * mu;
    float rs  = rsqrtf(var + 1e-5f);
    const float4 wv = ((const float4*)w)[t];
    const float4 bv = ((const float4*)b)[t];
    float4 o;
    o.x = (v.x - mu) * rs * wv.x + bv.x;
    o.y = (v.y - mu) * rs * wv.y + bv.y;
    o.z = (v.z - mu) * rs * wv.z + bv.z;
    o.w = (v.w - mu) * rs * wv.w + bv.w;
    ((float4*)(y + (size_t)row * EMB))[t] = o;
}

// ---------------- tf32 mma.sync GEMM: C[M,Nn] = A[M,K]*B[Nn,K]^T ----------------
#define GBM 128
#define GBN 256
#define GBK 32
#define GPITCH 36
#define A_STAGE_F (GBM * GPITCH)
#define B_STAGE_F (GBN * GPITCH)
#define STAGE_F   (A_STAGE_F + B_STAGE_F)
#define G_SMEM_BYTES (2 * STAGE_F * 4)

template <int ACT>
__global__ __launch_bounds__(256, 1)
void gemm_tc(const float* __restrict__ A, const float* __restrict__ B,
             const float* __restrict__ bias, const float* __restrict__ res,
             float* __restrict__ C, int M, int Nn, int K) {
    extern __shared__ float sm[];
    uint32_t smemBase = smem_u32(sm);
    int t = threadIdx.x;
    int w = t >> 5, lane = t & 31;
    int g = lane >> 2, c = lane & 3;
    int wm = w & 1, wn = w >> 1;
    int m0 = blockIdx.y * GBM;
    int n0 = blockIdx.x * GBN;
    int KT = K / GBK;

    const float* Ab = A + (size_t)m0 * K;
    const float* Bb = B + (size_t)n0 * K;

    float d[4][8][4];
    #pragma unroll
    for (int i = 0; i < 4; i++)
        #pragma unroll
        for (int j = 0; j < 8; j++)
            #pragma unroll
            for (int q = 0; q < 4; q++) d[i][j][q] = 0.f;

    auto load_stage = [&](int s, int k0) {
        uint32_t aS = smemBase + (uint32_t)(s * STAGE_F * 4);
        uint32_t bS = aS + A_STAGE_F * 4;
        #pragma unroll
        for (int i = 0; i < 4; i++) {
            int ch = t + i * 256;
            int row = ch >> 3, cc = ch & 7;
            cp16(aS + (uint32_t)(row * GPITCH + cc * 4) * 4,
                 Ab + (size_t)row * K + k0 + cc * 4);
        }
        #pragma unroll
        for (int i = 0; i < 8; i++) {
            int ch = t + i * 256;
            int row = ch >> 3, cc = ch & 7;
            cp16(bS + (uint32_t)(row * GPITCH + cc * 4) * 4,
                 Bb + (size_t)row * K + k0 + cc * 4);
        }
    };

    load_stage(0, 0);
    CP_COMMIT();

    for (int kt = 0; kt < KT; kt++) {
        if (kt + 1 < KT) {
            load_stage((kt + 1) & 1, (kt + 1) * GBK);
            CP_COMMIT();
            asm volatile("cp.async.wait_group 1;" ::: "memory");
        } else {
            asm volatile("cp.async.wait_group 0;" ::: "memory");
        }
        __syncthreads();

        const float* As = sm + (kt & 1) * STAGE_F;
        const float* Bs = As + A_STAGE_F;

        #pragma unroll
        for (int kk = 0; kk < GBK / 8; kk++) {
            int kc = kk * 8;
            uint32_t a[4][4], b[8][2];
            #pragma unroll
            for (int i = 0; i < 4; i++) {
                int r = wm * 64 + i * 16 + g;
                const float* p0 = As + r * GPITCH + kc + c;
                const float* p1 = As + (r + 8) * GPITCH + kc + c;
                a[i][0] = f2tf(p0[0]);
                a[i][1] = f2tf(p1[0]);
                a[i][2] = f2tf(p0[4]);
                a[i][3] = f2tf(p1[4]);
            }
            #pragma unroll
            for (int j = 0; j < 8; j++) {
                int n = wn * 64 + j * 8 + g;
                const float* p = Bs + n * GPITCH + kc + c;
                b[j][0] = __float_as_uint(p[0]);     // raw fp32: HW truncates to tf32
                b[j][1] = __float_as_uint(p[4]);
            }
            #pragma unroll
            for (int i = 0; i < 4; i++)
                #pragma unroll
                for (int j = 0; j < 8; j++)
                    mma_tf32(d[i][j], a[i], b[j]);
        }
        __syncthreads();
    }

    #pragma unroll
    for (int i = 0; i < 4; i++) {
        int row0 = m0 + wm * 64 + i * 16 + g;
        #pragma unroll
        for (int j = 0; j < 8; j++) {
            int col = n0 + wn * 64 + j * 8 + 2 * c;
            float2 bv = *(const float2*)(bias + col);
            float v0 = d[i][j][0] + bv.x;
            float v1 = d[i][j][1] + bv.y;
            float v2 = d[i][j][2] + bv.x;
            float v3 = d[i][j][3] + bv.y;
            if (ACT == 1) {
                v0 = 0.5f * v0 * (1.0f + erff(v0 * 0.70710678118f));
                v1 = 0.5f * v1 * (1.0f + erff(v1 * 0.70710678118f));
                v2 = 0.5f * v2 * (1.0f + erff(v2 * 0.70710678118f));
                v3 = 0.5f * v3 * (1.0f + erff(v3 * 0.70710678118f));
            }
            if (res != nullptr) {
                float2 r0 = *(const float2*)(res + (size_t)row0 * Nn + col);
                float2 r1 = *(const float2*)(res + (size_t)(row0 + 8) * Nn + col);
                v0 += r0.x; v1 += r0.y; v2 += r1.x; v3 += r1.y;
            }
            float2 o0 = {v0, v1}, o1 = {v2, v3};
            *(float2*)(C + (size_t)row0 * Nn + col) = o0;
            *(float2*)(C + (size_t)(row0 + 8) * Nn + col) = o1;
        }
    }
}

// ---------------- Flash attention on tensor cores (tf32 mma.sync) ---------------
// grid (L/128, NB*NHEAD), 256 threads = 8 warps, warp owns 16 q-rows.
// Per 64-key tile: S = Q K^T via mma; softmax in registers (quad shfl);
// P->A-operand layout conversion via shfl; PV via mma against V^T in smem.
#define ATP 68   /* smem pitch: 68 % 32 == 4 -> banks 4g+c conflict-free */

__global__ __launch_bounds__(256, 1) void attn_tc(
    const float* __restrict__ qkv, float* __restrict__ out) {
    __shared__ float KS[64 * ATP];
    __shared__ float VT[64 * ATP];

    int t = threadIdx.x;
    int w = t >> 5, lane = t & 31;
    int g = lane >> 2, c = lane & 3;
    int bh = blockIdx.y;
    int n  = bh >> 4;
    int h  = bh & 15;
    int q0 = blockIdx.x * 128;
    int hcol = h * HDIM;

    // ---- Q fragments (once, registers), scaled + tf32-rounded ----
    uint32_t qf[8][4];
    {
        int r0 = q0 + w * 16 + g;
        const float* qp0 = qkv + ((size_t)(r0 * NB + n)) * (3 * EMB) + hcol;
        const float* qp1 = qkv + ((size_t)((r0 + 8) * NB + n)) * (3 * EMB) + hcol;
        #pragma unroll
        for (int kc = 0; kc < 8; kc++) {
            qf[kc][0] = f2tf(qp0[kc * 8 + c] * QSCALE);
            qf[kc][1] = f2tf(qp1[kc * 8 + c] * QSCALE);
            qf[kc][2] = f2tf(qp0[kc * 8 + c + 4] * QSCALE);
            qf[kc][3] = f2tf(qp1[kc * 8 + c + 4] * QSCALE);
        }
    }

    float o_[8][4];
    #pragma unroll
    for (int j = 0; j < 8; j++)
        #pragma unroll
        for (int q = 0; q < 4; q++) o_[j][q] = 0.f;
    float m0 = -1e30f, m1 = -1e30f, l0 = 0.f, l1 = 0.f;

    int srcLo = (lane & ~3) | (c >> 1);
    int srcHi = srcLo + 2;

    for (int kt = 0; kt < L_SEQ / 64; kt++) {
        int k0 = kt * 64;
        __syncthreads();   // previous tile's compute done before overwrite

        // K tile: [key][d], coalesced float4
        #pragma unroll
        for (int i = 0; i < 4; i++) {
            int idx = i * 256 + t;
            int r = idx >> 4, u = idx & 15;
            float4 kv = *(const float4*)(qkv + ((size_t)((k0 + r) * NB + n)) * (3 * EMB)
                                          + EMB + hcol + u * 4);
            *(float4*)&KS[r * ATP + u * 4] = kv;
        }
        // V tile transposed: VT[d][key]
        #pragma unroll
        for (int i = 0; i < 4; i++) {
            int idx = i * 256 + t;
            int u2 = idx & 7, r = (idx >> 3) & 63, half = idx >> 9;
            int dc = (u2 + half * 8) * 4;
            float4 vv = *(const float4*)(qkv + ((size_t)((k0 + r) * NB + n)) * (3 * EMB)
                                          + 2 * EMB + hcol + dc);
            VT[(dc + 0) * ATP + r] = vv.x;
            VT[(dc + 1) * ATP + r] = vv.y;
            VT[(dc + 2) * ATP + r] = vv.z;
            VT[(dc + 3) * ATP + r] = vv.w;
        }
        __syncthreads();

        // ---- scores: S[16q x 64k] ----
        float s[8][4];
        #pragma unroll
        for (int j = 0; j < 8; j++)
            #pragma unroll
            for (int q = 0; q < 4; q++) s[j][q] = 0.f;
        #pragma unroll
        for (int kc = 0; kc < 8; kc++) {
            #pragma unroll
            for (int j = 0; j < 8; j++) {
                uint32_t b[2];
                const float* kp = &KS[(8 * j + g) * ATP + kc * 8 + c];
                b[0] = __float_as_uint(kp[0]);
                b[1] = __float_as_uint(kp[4]);
                mma_tf32(s[j], qf[kc], b);
            }
        }

        // ---- online softmax (registers + quad shfl) ----
        float mx0 = s[0][0], mx1 = s[0][2];
        #pragma unroll
        for (int j = 0; j < 8; j++) {
            mx0 = fmaxf(mx0, fmaxf(s[j][0], s[j][1]));
            mx1 = fmaxf(mx1, fmaxf(s[j][2], s[j][3]));
        }
        mx0 = fmaxf(mx0, __shfl_xor_sync(0xffffffffu, mx0, 1));
        mx0 = fmaxf(mx0, __shfl_xor_sync(0xffffffffu, mx0, 2));
        mx1 = fmaxf(mx1, __shfl_xor_sync(0xffffffffu, mx1, 1));
        mx1 = fmaxf(mx1, __shfl_xor_sync(0xffffffffu, mx1, 2));
        float nm0 = fmaxf(m0, mx0), nm1 = fmaxf(m1, mx1);
        float corr0 = fexp(m0 - nm0), corr1 = fexp(m1 - nm1);
        m0 = nm0; m1 = nm1;
        float sum0 = 0.f, sum1 = 0.f;
        #pragma unroll
        for (int j = 0; j < 8; j++) {
            s[j][0] = fexp(s[j][0] - m0);
            s[j][1] = fexp(s[j][1] - m0);
            s[j][2] = fexp(s[j][2] - m1);
            s[j][3] = fexp(s[j][3] - m1);
            sum0 += s[j][0] + s[j][1];
            sum1 += s[j][2] + s[j][3];
        }
        sum0 += __shfl_xor_sync(0xffffffffu, sum0, 1);
        sum0 += __shfl_xor_sync(0xffffffffu, sum0, 2);
        sum1 += __shfl_xor_sync(0xffffffffu, sum1, 1);
        sum1 += __shfl_xor_sync(0xffffffffu, sum1, 2);
        l0 = l0 * corr0 + sum0;
        l1 = l1 * corr1 + sum1;
        #pragma unroll
        for (int j = 0; j < 8; j++) {
            o_[j][0] *= corr0; o_[j][1] *= corr0;
            o_[j][2] *= corr1; o_[j][3] *= corr1;
        }

        // ---- PV: layout-convert P via shfl, mma against VT ----
        #pragma unroll
        for (int kc = 0; kc < 8; kc++) {
            float t00 = __shfl_sync(0xffffffffu, s[kc][0], srcLo);
            float t01 = __shfl_sync(0xffffffffu, s[kc][1], srcLo);
            float t10 = __shfl_sync(0xffffffffu, s[kc][2], srcLo);
            float t11 = __shfl_sync(0xffffffffu, s[kc][3], srcLo);
            float t20 = __shfl_sync(0xffffffffu, s[kc][0], srcHi);
            float t21 = __shfl_sync(0xffffffffu, s[kc][1], srcHi);
            float t30 = __shfl_sync(0xffffffffu, s[kc][2], srcHi);
            float t31 = __shfl_sync(0xffffffffu, s[kc][3], srcHi);
            uint32_t pa[4];
            pa[0] = f2tf((c & 1) ? t01 : t00);
            pa[1] = f2tf((c & 1) ? t11 : t10);
            pa[2] = f2tf((c & 1) ? t21 : t20);
            pa[3] = f2tf((c & 1) ? t31 : t30);
            #pragma unroll
            for (int j = 0; j < 8; j++) {
                uint32_t b[2];
                const float* vp = &VT[(8 * j + g) * ATP + kc * 8 + c];
                b[0] = __float_as_uint(vp[0]);
                b[1] = __float_as_uint(vp[4]);
                mma_tf32(o_[j], pa, b);
            }
        }
    }

    // ---- write output ----
    float inv0 = 1.0f / l0, inv1 = 1.0f / l1;
    int r0 = q0 + w * 16 + g;
    float* out0 = out + ((size_t)(r0 * NB + n)) * EMB + hcol;
    float* out1 = out + ((size_t)((r0 + 8) * NB + n)) * EMB + hcol;
    #pragma unroll
    for (int j = 0; j < 8; j++) {
        int col = 8 * j + 2 * c;
        float2 a = {o_[j][0] * inv0, o_[j][1] * inv0};
        float2 b = {o_[j][2] * inv1, o_[j][3] * inv1};
        *(float2*)(out0 + col) = a;
        *(float2*)(out1 + col) = b;
    }
}

// ---------------- driver --------------------------------------------------------
extern "C" void kernel_launch(void* const* d_in, const int* in_sizes, int n_in,
                              void* d_out, int out_size) {
    const float* x         = (const float*)d_in[0];
    const float* ln1_w     = (const float*)d_in[1];
    const float* ln1_b     = (const float*)d_in[2];
    const float* in_proj_w = (const float*)d_in[3];
    const float* in_proj_b = (const float*)d_in[4];
    const float* out_w     = (const float*)d_in[5];
    const float* out_b     = (const float*)d_in[6];
    const float* ln2_w     = (const float*)d_in[7];
    const float* ln2_b     = (const float*)d_in[8];
    const float* fc_w      = (const float*)d_in[9];
    const float* fc_b      = (const float*)d_in[10];
    const float* proj_w    = (const float*)d_in[11];
    const float* proj_b    = (const float*)d_in[12];
    float* out = (float*)d_out;

    float *y, *qkv, *o, *x1, *hbuf;
    cudaGetSymbolAddress((void**)&y,    g_y);
    cudaGetSymbolAddress((void**)&qkv,  g_qkv);
    cudaGetSymbolAddress((void**)&o,    g_o);
    cudaGetSymbolAddress((void**)&x1,   g_x1);
    cudaGetSymbolAddress((void**)&hbuf, g_h);

    static bool attr_done = false;
    if (!attr_done) {
        cudaFuncSetAttribute(gemm_tc<0>, cudaFuncAttributeMaxDynamicSharedMemorySize, G_SMEM_BYTES);
        cudaFuncSetAttribute(gemm_tc<1>, cudaFuncAttributeMaxDynamicSharedMemorySize, G_SMEM_BYTES);
        attr_done = true;
    }

    // 1. y = LN1(x)
    ln_kernel<<<ROWS, 256>>>(x, ln1_w, ln1_b, y);
    // 2. qkv = y @ in_proj_w^T + in_proj_b
    gemm_tc<0><<<dim3(3 * EMB / GBN, ROWS / GBM), 256, G_SMEM_BYTES>>>(
        y, in_proj_w, in_proj_b, nullptr, qkv, ROWS, 3 * EMB, EMB);
    // 3. o = attention(qkv)
    attn_tc<<<dim3(L_SEQ / 128, NB * NHEAD), 256>>>(qkv, o);
    // 4. x1 = x + o @ out_w^T + out_b
    gemm_tc<0><<<dim3(EMB / GBN, ROWS / GBM), 256, G_SMEM_BYTES>>>(
        o, out_w, out_b, x, x1, ROWS, EMB, EMB);
    // 5. y = LN2(x1)
    ln_kernel<<<ROWS, 256>>>(x1, ln2_w, ln2_b, y);
    // 6. h = GELU(y @ fc_w^T + fc_b)
    gemm_tc<1><<<dim3(FFN / GBN, ROWS / GBM), 256, G_SMEM_BYTES>>>(
        y, fc_w, fc_b, nullptr, hbuf, ROWS, FFN, EMB);
    // 7. out = x1 + h @ proj_w^T + proj_b
    gemm_tc<0><<<dim3(EMB / GBN, ROWS / GBM), 256, G_SMEM_BYTES>>>(
        hbuf, proj_w, proj_b, x1, out, ROWS, EMB, FFN);
}

// round 5
// speedup vs baseline: 5.1434x; 1.0324x over previous
#include <cuda_runtime.h>
#include <math.h>
#include <stdint.h>

#define L_SEQ 2048
#define NB    2
#define EMB   1024
#define NHEAD 16
#define HDIM  64
#define ROWS  (L_SEQ * NB)   /* 4096 */
#define FFN   (4 * EMB)      /* 4096 */
#define QSCALE (1.0f / 64.0f)

// ---------------- scratch (no allocation allowed; __device__ globals) ----------
__device__ float g_y[(size_t)ROWS * EMB];
__device__ float g_qkv[(size_t)ROWS * 3 * EMB];
__device__ float g_o[(size_t)ROWS * EMB];
__device__ float g_x1[(size_t)ROWS * EMB];
__device__ float g_h[(size_t)ROWS * FFN];

// ---------------- helpers -------------------------------------------------------
__device__ __forceinline__ uint32_t smem_u32(const void* p) {
    uint32_t a;
    asm("{ .reg .u64 t; cvta.to.shared.u64 t, %1; cvt.u32.u64 %0, t; }" : "=r"(a) : "l"(p));
    return a;
}
__device__ __forceinline__ void cp16(uint32_t s, const void* g) {
    asm volatile("cp.async.cg.shared.global [%0], [%1], 16;" :: "r"(s), "l"(g) : "memory");
}
#define CP_COMMIT() asm volatile("cp.async.commit_group;" ::: "memory")

__device__ __forceinline__ uint32_t f2tf(float f) {
    uint32_t u; asm("cvt.rna.tf32.f32 %0, %1;" : "=r"(u) : "f"(f)); return u;
}
__device__ __forceinline__ float tfr(float f) {          // round value to tf32-RN
    return __uint_as_float(f2tf(f));
}
__device__ __forceinline__ void mma_tf32(float* d, const uint32_t* a, const uint32_t* b) {
    asm volatile(
        "mma.sync.aligned.m16n8k8.row.col.f32.tf32.tf32.f32 "
        "{%0,%1,%2,%3}, {%4,%5,%6,%7}, {%8,%9}, {%0,%1,%2,%3};"
        : "+f"(d[0]), "+f"(d[1]), "+f"(d[2]), "+f"(d[3])
        : "r"(a[0]), "r"(a[1]), "r"(a[2]), "r"(a[3]), "r"(b[0]), "r"(b[1]));
}
__device__ __forceinline__ void ldsm4(uint32_t* r, uint32_t addr) {
    asm volatile("ldmatrix.sync.aligned.m8n8.x4.shared.b16 {%0,%1,%2,%3}, [%4];"
                 : "=r"(r[0]), "=r"(r[1]), "=r"(r[2]), "=r"(r[3]) : "r"(addr));
}

// fast exp: FFMA-only, rel err ~1e-7
__device__ __forceinline__ float fexp(float x) {
    x = fmaxf(x, -80.0f);
    float t = x * 1.4426950408889634f;
    float r = t + 12582912.0f;
    float i = r - 12582912.0f;
    float f = t - i;
    float p = 1.3333558146428443e-3f;
    p = fmaf(p, f, 9.6181291076284772e-3f);
    p = fmaf(p, f, 5.5504108664821580e-2f);
    p = fmaf(p, f, 2.4022650695910072e-1f);
    p = fmaf(p, f, 6.9314718055994531e-1f);
    p = fmaf(p, f, 1.0f);
    return p * __int_as_float(((int)i + 127) << 23);
}

// ---------------- LayerNorm (output rounded to tf32: feeds GEMM A operands) ----
__global__ void ln_kernel(const float* __restrict__ x,
                          const float* __restrict__ w,
                          const float* __restrict__ b,
                          float* __restrict__ y) {
    int row = blockIdx.x;
    int t = threadIdx.x;
    const float4 v = ((const float4*)(x + (size_t)row * EMB))[t];
    float s  = v.x + v.y + v.z + v.w;
    float sq = v.x * v.x + v.y * v.y + v.z * v.z + v.w * v.w;
    #pragma unroll
    for (int o = 16; o; o >>= 1) {
        s  += __shfl_xor_sync(0xffffffffu, s, o);
        sq += __shfl_xor_sync(0xffffffffu, sq, o);
    }
    __shared__ float ss[8], ssq[8];
    int wid = t >> 5, lid = t & 31;
    if (lid == 0) { ss[wid] = s; ssq[wid] = sq; }
    __syncthreads();
    if (t == 0) {
        float a = 0.f, c = 0.f;
        #pragma unroll
        for (int i = 0; i < 8; i++) { a += ss[i]; c += ssq[i]; }
        ss[0] = a; ssq[0] = c;
    }
    __syncthreads();
    float mu  = ss[0] * (1.0f / EMB);
    float var = ssq[0] * (1.0f / EMB) - mu * mu;
    float rs  = rsqrtf(var + 1e-5f);
    const float4 wv = ((const float4*)w)[t];
    const float4 bv = ((const float4*)b)[t];
    float4 o;
    o.x = tfr((v.x - mu) * rs * wv.x + bv.x);
    o.y = tfr((v.y - mu) * rs * wv.y + bv.y);
    o.z = tfr((v.z - mu) * rs * wv.z + bv.z);
    o.w = tfr((v.w - mu) * rs * wv.w + bv.w);
    ((float4*)(y + (size_t)row * EMB))[t] = o;
}

// ---------------- tf32 mma.sync GEMM: C[M,Nn] = A[M,K]*B[Nn,K]^T ----------------
// Block 128x256, BK=32, 8 warps 2x4, warp tile 64x64. ldmatrix fragment loads.
#define GBM 128
#define GBN 256
#define GBK 32
#define GPITCH 36
#define A_STAGE_F (GBM * GPITCH)
#define B_STAGE_F (GBN * GPITCH)
#define STAGE_F   (A_STAGE_F + B_STAGE_F)
#define G_SMEM_BYTES (2 * STAGE_F * 4)

template <int ACT>
__global__ __launch_bounds__(256, 1)
void gemm_tc(const float* __restrict__ A, const float* __restrict__ B,
             const float* __restrict__ bias, const float* __restrict__ res,
             float* __restrict__ C, int M, int Nn, int K) {
    extern __shared__ float sm[];
    uint32_t smemBase = smem_u32(sm);
    int t = threadIdx.x;
    int w = t >> 5, lane = t & 31;
    int g = lane >> 2, c = lane & 3;
    int wm = w & 1, wn = w >> 1;
    int m0 = blockIdx.y * GBM;
    int n0 = blockIdx.x * GBN;
    int KT = K / GBK;

    const float* Ab = A + (size_t)m0 * K;
    const float* Bb = B + (size_t)n0 * K;

    // ldmatrix per-lane address roles
    const uint32_t aOff = (uint32_t)(((wm * 64 + (lane & 15)) * GPITCH
                                     + ((lane >> 4) * 4)) * 4);
    const uint32_t bOff = (uint32_t)(A_STAGE_F * 4)
                        + (uint32_t)(((wn * 64 + ((lane >> 4) * 8) + (lane & 7)) * GPITCH
                                     + (((lane >> 3) & 1) * 4)) * 4);

    float d[4][8][4];
    #pragma unroll
    for (int i = 0; i < 4; i++)
        #pragma unroll
        for (int j = 0; j < 8; j++)
            #pragma unroll
            for (int q = 0; q < 4; q++) d[i][j][q] = 0.f;

    auto load_stage = [&](int s, int k0) {
        uint32_t aS = smemBase + (uint32_t)(s * STAGE_F * 4);
        uint32_t bS = aS + A_STAGE_F * 4;
        #pragma unroll
        for (int i = 0; i < 4; i++) {
            int ch = t + i * 256;
            int row = ch >> 3, cc = ch & 7;
            cp16(aS + (uint32_t)(row * GPITCH + cc * 4) * 4,
                 Ab + (size_t)row * K + k0 + cc * 4);
        }
        #pragma unroll
        for (int i = 0; i < 8; i++) {
            int ch = t + i * 256;
            int row = ch >> 3, cc = ch & 7;
            cp16(bS + (uint32_t)(row * GPITCH + cc * 4) * 4,
                 Bb + (size_t)row * K + k0 + cc * 4);
        }
    };

    load_stage(0, 0);
    CP_COMMIT();

    for (int kt = 0; kt < KT; kt++) {
        if (kt + 1 < KT) {
            load_stage((kt + 1) & 1, (kt + 1) * GBK);
            CP_COMMIT();
            asm volatile("cp.async.wait_group 1;" ::: "memory");
        } else {
            asm volatile("cp.async.wait_group 0;" ::: "memory");
        }
        __syncthreads();

        uint32_t stBase = smemBase + (uint32_t)((kt & 1) * STAGE_F * 4);
        uint32_t aAddr = stBase + aOff;
        uint32_t bAddr = stBase + bOff;

        #pragma unroll
        for (int kk = 0; kk < GBK / 8; kk++) {
            uint32_t kc4 = (uint32_t)(kk * 8 * 4);     // byte offset within row
            uint32_t a[4][4], b[4][4];
            #pragma unroll
            for (int i = 0; i < 4; i++)
                ldsm4(a[i], aAddr + (uint32_t)(i * 16 * GPITCH * 4) + kc4);
            #pragma unroll
            for (int jp = 0; jp < 4; jp++)
                ldsm4(b[jp], bAddr + (uint32_t)(jp * 16 * GPITCH * 4) + kc4);
            #pragma unroll
            for (int i = 0; i < 4; i++)
                #pragma unroll
                for (int j = 0; j < 8; j++)
                    mma_tf32(d[i][j], a[i], &b[j >> 1][(j & 1) * 2]);
        }
        __syncthreads();
    }

    #pragma unroll
    for (int i = 0; i < 4; i++) {
        int row0 = m0 + wm * 64 + i * 16 + g;
        #pragma unroll
        for (int j = 0; j < 8; j++) {
            int col = n0 + wn * 64 + j * 8 + 2 * c;
            float2 bv = *(const float2*)(bias + col);
            float v0 = d[i][j][0] + bv.x;
            float v1 = d[i][j][1] + bv.y;
            float v2 = d[i][j][2] + bv.x;
            float v3 = d[i][j][3] + bv.y;
            if (ACT == 1) {
                // exact GELU, then round: h feeds the proj GEMM as A operand
                v0 = tfr(0.5f * v0 * (1.0f + erff(v0 * 0.70710678118f)));
                v1 = tfr(0.5f * v1 * (1.0f + erff(v1 * 0.70710678118f)));
                v2 = tfr(0.5f * v2 * (1.0f + erff(v2 * 0.70710678118f)));
                v3 = tfr(0.5f * v3 * (1.0f + erff(v3 * 0.70710678118f)));
            }
            if (res != nullptr) {
                float2 r0 = *(const float2*)(res + (size_t)row0 * Nn + col);
                float2 r1 = *(const float2*)(res + (size_t)(row0 + 8) * Nn + col);
                v0 += r0.x; v1 += r0.y; v2 += r1.x; v3 += r1.y;
            }
            float2 o0 = {v0, v1}, o1 = {v2, v3};
            *(float2*)(C + (size_t)row0 * Nn + col) = o0;
            *(float2*)(C + (size_t)(row0 + 8) * Nn + col) = o1;
        }
    }
}

// ---------------- Flash attention on tensor cores (tf32 mma.sync + ldmatrix) ----
#define ATP 68   /* smem pitch: rows walk banks by 4 -> conflict-free */

__global__ __launch_bounds__(256, 1) void attn_tc(
    const float* __restrict__ qkv, float* __restrict__ out) {
    __shared__ float KS[64 * ATP];
    __shared__ float VT[64 * ATP];

    int t = threadIdx.x;
    int w = t >> 5, lane = t & 31;
    int g = lane >> 2, c = lane & 3;
    int bh = blockIdx.y;
    int n  = bh >> 4;
    int h  = bh & 15;
    int q0 = blockIdx.x * 128;
    int hcol = h * HDIM;

    // B-operand ldmatrix lane offset (shared by K and VT phases)
    const uint32_t bROff = (uint32_t)(((((lane >> 4) * 8) + (lane & 7)) * ATP
                                      + (((lane >> 3) & 1) * 4)) * 4);
    const uint32_t ksBase = smem_u32(KS) + bROff;
    const uint32_t vtBase = smem_u32(VT) + bROff;

    // ---- Q fragments (once, registers), scaled + tf32-rounded ----
    uint32_t qf[8][4];
    {
        int r0 = q0 + w * 16 + g;
        const float* qp0 = qkv + ((size_t)(r0 * NB + n)) * (3 * EMB) + hcol;
        const float* qp1 = qkv + ((size_t)((r0 + 8) * NB + n)) * (3 * EMB) + hcol;
        #pragma unroll
        for (int kc = 0; kc < 8; kc++) {
            qf[kc][0] = f2tf(qp0[kc * 8 + c] * QSCALE);
            qf[kc][1] = f2tf(qp1[kc * 8 + c] * QSCALE);
            qf[kc][2] = f2tf(qp0[kc * 8 + c + 4] * QSCALE);
            qf[kc][3] = f2tf(qp1[kc * 8 + c + 4] * QSCALE);
        }
    }

    float o_[8][4];
    #pragma unroll
    for (int j = 0; j < 8; j++)
        #pragma unroll
        for (int q = 0; q < 4; q++) o_[j][q] = 0.f;
    float m0 = -1e30f, m1 = -1e30f, l0 = 0.f, l1 = 0.f;

    int srcLo = (lane & ~3) | (c >> 1);
    int srcHi = srcLo + 2;

    for (int kt = 0; kt < L_SEQ / 64; kt++) {
        int k0 = kt * 64;
        __syncthreads();

        // K tile: [key][d]
        #pragma unroll
        for (int i = 0; i < 4; i++) {
            int idx = i * 256 + t;
            int r = idx >> 4, u = idx & 15;
            float4 kv = *(const float4*)(qkv + ((size_t)((k0 + r) * NB + n)) * (3 * EMB)
                                          + EMB + hcol + u * 4);
            *(float4*)&KS[r * ATP + u * 4] = kv;
        }
        // V tile transposed: VT[d][key]
        #pragma unroll
        for (int i = 0; i < 4; i++) {
            int idx = i * 256 + t;
            int u2 = idx & 7, r = (idx >> 3) & 63, half = idx >> 9;
            int dc = (u2 + half * 8) * 4;
            float4 vv = *(const float4*)(qkv + ((size_t)((k0 + r) * NB + n)) * (3 * EMB)
                                          + 2 * EMB + hcol + dc);
            VT[(dc + 0) * ATP + r] = vv.x;
            VT[(dc + 1) * ATP + r] = vv.y;
            VT[(dc + 2) * ATP + r] = vv.z;
            VT[(dc + 3) * ATP + r] = vv.w;
        }
        __syncthreads();

        // ---- scores: S[16q x 64k] via ldmatrix + mma ----
        float s[8][4];
        #pragma unroll
        for (int j = 0; j < 8; j++)
            #pragma unroll
            for (int q = 0; q < 4; q++) s[j][q] = 0.f;
        #pragma unroll
        for (int kc = 0; kc < 8; kc++) {
            #pragma unroll
            for (int jp = 0; jp < 4; jp++) {
                uint32_t bf[4];
                ldsm4(bf, ksBase + (uint32_t)(jp * 16 * ATP * 4) + (uint32_t)(kc * 32));
                mma_tf32(s[2 * jp],     qf[kc], &bf[0]);
                mma_tf32(s[2 * jp + 1], qf[kc], &bf[2]);
            }
        }

        // ---- online softmax (registers + quad shfl) ----
        float mx0 = s[0][0], mx1 = s[0][2];
        #pragma unroll
        for (int j = 0; j < 8; j++) {
            mx0 = fmaxf(mx0, fmaxf(s[j][0], s[j][1]));
            mx1 = fmaxf(mx1, fmaxf(s[j][2], s[j][3]));
        }
        mx0 = fmaxf(mx0, __shfl_xor_sync(0xffffffffu, mx0, 1));
        mx0 = fmaxf(mx0, __shfl_xor_sync(0xffffffffu, mx0, 2));
        mx1 = fmaxf(mx1, __shfl_xor_sync(0xffffffffu, mx1, 1));
        mx1 = fmaxf(mx1, __shfl_xor_sync(0xffffffffu, mx1, 2));
        float nm0 = fmaxf(m0, mx0), nm1 = fmaxf(m1, mx1);
        float corr0 = fexp(m0 - nm0), corr1 = fexp(m1 - nm1);
        m0 = nm0; m1 = nm1;
        float sum0 = 0.f, sum1 = 0.f;
        #pragma unroll
        for (int j = 0; j < 8; j++) {
            s[j][0] = fexp(s[j][0] - m0);
            s[j][1] = fexp(s[j][1] - m0);
            s[j][2] = fexp(s[j][2] - m1);
            s[j][3] = fexp(s[j][3] - m1);
            sum0 += s[j][0] + s[j][1];
            sum1 += s[j][2] + s[j][3];
        }
        sum0 += __shfl_xor_sync(0xffffffffu, sum0, 1);
        sum0 += __shfl_xor_sync(0xffffffffu, sum0, 2);
        sum1 += __shfl_xor_sync(0xffffffffu, sum1, 1);
        sum1 += __shfl_xor_sync(0xffffffffu, sum1, 2);
        l0 = l0 * corr0 + sum0;
        l1 = l1 * corr1 + sum1;
        #pragma unroll
        for (int j = 0; j < 8; j++) {
            o_[j][0] *= corr0; o_[j][1] *= corr0;
            o_[j][2] *= corr1; o_[j][3] *= corr1;
        }

        // ---- PV: layout-convert P via shfl, ldmatrix VT, mma ----
        #pragma unroll
        for (int kc = 0; kc < 8; kc++) {
            float t00 = __shfl_sync(0xffffffffu, s[kc][0], srcLo);
            float t01 = __shfl_sync(0xffffffffu, s[kc][1], srcLo);
            float t10 = __shfl_sync(0xffffffffu, s[kc][2], srcLo);
            float t11 = __shfl_sync(0xffffffffu, s[kc][3], srcLo);
            float t20 = __shfl_sync(0xffffffffu, s[kc][0], srcHi);
            float t21 = __shfl_sync(0xffffffffu, s[kc][1], srcHi);
            float t30 = __shfl_sync(0xffffffffu, s[kc][2], srcHi);
            float t31 = __shfl_sync(0xffffffffu, s[kc][3], srcHi);
            uint32_t pa[4];
            pa[0] = f2tf((c & 1) ? t01 : t00);
            pa[1] = f2tf((c & 1) ? t11 : t10);
            pa[2] = f2tf((c & 1) ? t21 : t20);
            pa[3] = f2tf((c & 1) ? t31 : t30);
            #pragma unroll
            for (int jp = 0; jp < 4; jp++) {
                uint32_t bf[4];
                ldsm4(bf, vtBase + (uint32_t)(jp * 16 * ATP * 4) + (uint32_t)(kc * 32));
                mma_tf32(o_[2 * jp],     pa, &bf[0]);
                mma_tf32(o_[2 * jp + 1], pa, &bf[2]);
            }
        }
    }

    // ---- write output (rounded: feeds out-proj GEMM as A operand) ----
    float inv0 = 1.0f / l0, inv1 = 1.0f / l1;
    int r0 = q0 + w * 16 + g;
    float* out0 = out + ((size_t)(r0 * NB + n)) * EMB + hcol;
    float* out1 = out + ((size_t)((r0 + 8) * NB + n)) * EMB + hcol;
    #pragma unroll
    for (int j = 0; j < 8; j++) {
        int col = 8 * j + 2 * c;
        float2 a = {tfr(o_[j][0] * inv0), tfr(o_[j][1] * inv0)};
        float2 b = {tfr(o_[j][2] * inv1), tfr(o_[j][3] * inv1)};
        *(float2*)(out0 + col) = a;
        *(float2*)(out1 + col) = b;
    }
}

// ---------------- driver --------------------------------------------------------
extern "C" void kernel_launch(void* const* d_in, const int* in_sizes, int n_in,
                              void* d_out, int out_size) {
    const float* x         = (const float*)d_in[0];
    const float* ln1_w     = (const float*)d_in[1];
    const float* ln1_b     = (const float*)d_in[2];
    const float* in_proj_w = (const float*)d_in[3];
    const float* in_proj_b = (const float*)d_in[4];
    const float* out_w     = (const float*)d_in[5];
    const float* out_b     = (const float*)d_in[6];
    const float* ln2_w     = (const float*)d_in[7];
    const float* ln2_b     = (const float*)d_in[8];
    const float* fc_w      = (const float*)d_in[9];
    const float* fc_b      = (const float*)d_in[10];
    const float* proj_w    = (const float*)d_in[11];
    const float* proj_b    = (const float*)d_in[12];
    float* out = (float*)d_out;

    float *y, *qkv, *o, *x1, *hbuf;
    cudaGetSymbolAddress((void**)&y,    g_y);
    cudaGetSymbolAddress((void**)&qkv,  g_qkv);
    cudaGetSymbolAddress((void**)&o,    g_o);
    cudaGetSymbolAddress((void**)&x1,   g_x1);
    cudaGetSymbolAddress((void**)&hbuf, g_h);

    static bool attr_done = false;
    if (!attr_done) {
        cudaFuncSetAttribute(gemm_tc<0>, cudaFuncAttributeMaxDynamicSharedMemorySize, G_SMEM_BYTES);
        cudaFuncSetAttribute(gemm_tc<1>, cudaFuncAttributeMaxDynamicSharedMemorySize, G_SMEM_BYTES);
        attr_done = true;
    }

    // 1. y = LN1(x)
    ln_kernel<<<ROWS, 256>>>(x, ln1_w, ln1_b, y);
    // 2. qkv = y @ in_proj_w^T + in_proj_b
    gemm_tc<0><<<dim3(3 * EMB / GBN, ROWS / GBM), 256, G_SMEM_BYTES>>>(
        y, in_proj_w, in_proj_b, nullptr, qkv, ROWS, 3 * EMB, EMB);
    // 3. o = attention(qkv)
    attn_tc<<<dim3(L_SEQ / 128, NB * NHEAD), 256>>>(qkv, o);
    // 4. x1 = x + o @ out_w^T + out_b
    gemm_tc<0><<<dim3(EMB / GBN, ROWS / GBM), 256, G_SMEM_BYTES>>>(
        o, out_w, out_b, x, x1, ROWS, EMB, EMB);
    // 5. y = LN2(x1)
    ln_kernel<<<ROWS, 256>>>(x1, ln2_w, ln2_b, y);
    // 6. h = GELU(y @ fc_w^T + fc_b)  (h rounded in epilogue)
    gemm_tc<1><<<dim3(FFN / GBN, ROWS / GBM), 256, G_SMEM_BYTES>>>(
        y, fc_w, fc_b, nullptr, hbuf, ROWS, FFN, EMB);
    // 7. out = x1 + h @ proj_w^T + proj_b
    gemm_tc<0><<<dim3(EMB / GBN, ROWS / GBM), 256, G_SMEM_BYTES>>>(
        hbuf, proj_w, proj_b, x1, out, ROWS, EMB, FFN);
}

// round 6
// speedup vs baseline: 5.4507x; 1.0598x over previous
#include <cuda_runtime.h>
#include <math.h>
#include <stdint.h>

#define L_SEQ 2048
#define NB    2
#define EMB   1024
#define NHEAD 16
#define HDIM  64
#define ROWS  (L_SEQ * NB)   /* 4096 */
#define FFN   (4 * EMB)      /* 4096 */
#define QSCALE (1.0f / 64.0f)

// ---------------- scratch (no allocation allowed; __device__ globals) ----------
__device__ float g_y[(size_t)ROWS * EMB];
__device__ float g_qkv[(size_t)ROWS * 3 * EMB];
__device__ float g_o[(size_t)ROWS * EMB];
__device__ float g_x1[(size_t)ROWS * EMB];
__device__ float g_h[(size_t)ROWS * FFN];

// ---------------- helpers -------------------------------------------------------
__device__ __forceinline__ uint32_t smem_u32(const void* p) {
    uint32_t a;
    asm("{ .reg .u64 t; cvta.to.shared.u64 t, %1; cvt.u32.u64 %0, t; }" : "=r"(a) : "l"(p));
    return a;
}
__device__ __forceinline__ void cp16(uint32_t s, const void* g) {
    asm volatile("cp.async.cg.shared.global [%0], [%1], 16;" :: "r"(s), "l"(g) : "memory");
}
#define CP_COMMIT() asm volatile("cp.async.commit_group;" ::: "memory")

__device__ __forceinline__ uint32_t f2tf(float f) {
    uint32_t u; asm("cvt.rna.tf32.f32 %0, %1;" : "=r"(u) : "f"(f)); return u;
}
__device__ __forceinline__ float tfr(float f) {          // round value to tf32-RN
    return __uint_as_float(f2tf(f));
}
__device__ __forceinline__ void mma_tf32(float* d, const uint32_t* a, const uint32_t* b) {
    asm volatile(
        "mma.sync.aligned.m16n8k8.row.col.f32.tf32.tf32.f32 "
        "{%0,%1,%2,%3}, {%4,%5,%6,%7}, {%8,%9}, {%0,%1,%2,%3};"
        : "+f"(d[0]), "+f"(d[1]), "+f"(d[2]), "+f"(d[3])
        : "r"(a[0]), "r"(a[1]), "r"(a[2]), "r"(a[3]), "r"(b[0]), "r"(b[1]));
}
__device__ __forceinline__ void ldsm4(uint32_t* r, uint32_t addr) {
    asm volatile("ldmatrix.sync.aligned.m8n8.x4.shared.b16 {%0,%1,%2,%3}, [%4];"
                 : "=r"(r[0]), "=r"(r[1]), "=r"(r[2]), "=r"(r[3]) : "r"(addr));
}

// fast exp: FFMA-only, rel err ~1e-7
__device__ __forceinline__ float fexp(float x) {
    x = fmaxf(x, -80.0f);
    float t = x * 1.4426950408889634f;
    float r = t + 12582912.0f;
    float i = r - 12582912.0f;
    float f = t - i;
    float p = 1.3333558146428443e-3f;
    p = fmaf(p, f, 9.6181291076284772e-3f);
    p = fmaf(p, f, 5.5504108664821580e-2f);
    p = fmaf(p, f, 2.4022650695910072e-1f);
    p = fmaf(p, f, 6.9314718055994531e-1f);
    p = fmaf(p, f, 1.0f);
    return p * __int_as_float(((int)i + 127) << 23);
}

// ---------------- LayerNorm (output rounded to tf32: feeds GEMM A operands) ----
__global__ void ln_kernel(const float* __restrict__ x,
                          const float* __restrict__ w,
                          const float* __restrict__ b,
                          float* __restrict__ y) {
    int row = blockIdx.x;
    int t = threadIdx.x;
    const float4 v = ((const float4*)(x + (size_t)row * EMB))[t];
    float s  = v.x + v.y + v.z + v.w;
    float sq = v.x * v.x + v.y * v.y + v.z * v.z + v.w * v.w;
    #pragma unroll
    for (int o = 16; o; o >>= 1) {
        s  += __shfl_xor_sync(0xffffffffu, s, o);
        sq += __shfl_xor_sync(0xffffffffu, sq, o);
    }
    __shared__ float ss[8], ssq[8];
    int wid = t >> 5, lid = t & 31;
    if (lid == 0) { ss[wid] = s; ssq[wid] = sq; }
    __syncthreads();
    if (t == 0) {
        float a = 0.f, c = 0.f;
        #pragma unroll
        for (int i = 0; i < 8; i++) { a += ss[i]; c += ssq[i]; }
        ss[0] = a; ssq[0] = c;
    }
    __syncthreads();
    float mu  = ss[0] * (1.0f / EMB);
    float var = ssq[0] * (1.0f / EMB) - mu * mu;
    float rs  = rsqrtf(var + 1e-5f);
    const float4 wv = ((const float4*)w)[t];
    const float4 bv = ((const float4*)b)[t];
    float4 o;
    o.x = tfr((v.x - mu) * rs * wv.x + bv.x);
    o.y = tfr((v.y - mu) * rs * wv.y + bv.y);
    o.z = tfr((v.z - mu) * rs * wv.z + bv.z);
    o.w = tfr((v.w - mu) * rs * wv.w + bv.w);
    ((float4*)(y + (size_t)row * EMB))[t] = o;
}

// ---------------- tf32 mma.sync GEMM: C[M,Nn] = A[M,K]*B[Nn,K]^T ----------------
// Block 128x128, BK=32, 8 warps 2x4, warp tile 64x32. 2 CTAs/SM target.
#define GBM 128
#define GBN 128
#define GBK 32
#define GPITCH 36
#define A_STAGE_F (GBM * GPITCH)
#define B_STAGE_F (GBN * GPITCH)
#define STAGE_F   (A_STAGE_F + B_STAGE_F)
#define G_SMEM_BYTES (2 * STAGE_F * 4)     /* 73728 bytes */

template <int ACT>
__global__ __launch_bounds__(256, 2)
void gemm_tc(const float* __restrict__ A, const float* __restrict__ B,
             const float* __restrict__ bias, const float* __restrict__ res,
             float* __restrict__ C, int M, int Nn, int K) {
    extern __shared__ float sm[];
    uint32_t smemBase = smem_u32(sm);
    int t = threadIdx.x;
    int w = t >> 5, lane = t & 31;
    int g = lane >> 2, c = lane & 3;
    int wm = w & 1, wn = w >> 1;                 // 2 x 4 warp grid
    int m0 = blockIdx.y * GBM;
    int n0 = blockIdx.x * GBN;
    int KT = K / GBK;

    const float* Ab = A + (size_t)m0 * K;
    const float* Bb = B + (size_t)n0 * K;

    // ldmatrix per-lane address roles
    const uint32_t aOff = (uint32_t)(((wm * 64 + (lane & 15)) * GPITCH
                                     + ((lane >> 4) * 4)) * 4);
    const uint32_t bOff = (uint32_t)(A_STAGE_F * 4)
                        + (uint32_t)(((wn * 32 + ((lane >> 4) * 8) + (lane & 7)) * GPITCH
                                     + (((lane >> 3) & 1) * 4)) * 4);

    float d[4][4][4];
    #pragma unroll
    for (int i = 0; i < 4; i++)
        #pragma unroll
        for (int j = 0; j < 4; j++)
            #pragma unroll
            for (int q = 0; q < 4; q++) d[i][j][q] = 0.f;

    auto load_stage = [&](int s, int k0) {
        uint32_t aS = smemBase + (uint32_t)(s * STAGE_F * 4);
        uint32_t bS = aS + A_STAGE_F * 4;
        #pragma unroll
        for (int i = 0; i < 4; i++) {
            int ch = t + i * 256;              // 0..1023
            int row = ch >> 3, cc = ch & 7;
            cp16(aS + (uint32_t)(row * GPITCH + cc * 4) * 4,
                 Ab + (size_t)row * K + k0 + cc * 4);
            cp16(bS + (uint32_t)(row * GPITCH + cc * 4) * 4,
                 Bb + (size_t)row * K + k0 + cc * 4);
        }
    };

    load_stage(0, 0);
    CP_COMMIT();

    for (int kt = 0; kt < KT; kt++) {
        if (kt + 1 < KT) {
            load_stage((kt + 1) & 1, (kt + 1) * GBK);
            CP_COMMIT();
            asm volatile("cp.async.wait_group 1;" ::: "memory");
        } else {
            asm volatile("cp.async.wait_group 0;" ::: "memory");
        }
        __syncthreads();

        uint32_t stBase = smemBase + (uint32_t)((kt & 1) * STAGE_F * 4);
        uint32_t aAddr = stBase + aOff;
        uint32_t bAddr = stBase + bOff;

        #pragma unroll
        for (int kk = 0; kk < GBK / 8; kk++) {
            uint32_t kc4 = (uint32_t)(kk * 8 * 4);
            uint32_t a[4][4], b[2][4];
            #pragma unroll
            for (int i = 0; i < 4; i++)
                ldsm4(a[i], aAddr + (uint32_t)(i * 16 * GPITCH * 4) + kc4);
            #pragma unroll
            for (int jp = 0; jp < 2; jp++)
                ldsm4(b[jp], bAddr + (uint32_t)(jp * 16 * GPITCH * 4) + kc4);
            #pragma unroll
            for (int i = 0; i < 4; i++)
                #pragma unroll
                for (int j = 0; j < 4; j++)
                    mma_tf32(d[i][j], a[i], &b[j >> 1][(j & 1) * 2]);
        }
        __syncthreads();
    }

    #pragma unroll
    for (int i = 0; i < 4; i++) {
        int row0 = m0 + wm * 64 + i * 16 + g;
        #pragma unroll
        for (int j = 0; j < 4; j++) {
            int col = n0 + wn * 32 + j * 8 + 2 * c;
            float2 bv = *(const float2*)(bias + col);
            float v0 = d[i][j][0] + bv.x;
            float v1 = d[i][j][1] + bv.y;
            float v2 = d[i][j][2] + bv.x;
            float v3 = d[i][j][3] + bv.y;
            if (ACT == 1) {
                v0 = tfr(0.5f * v0 * (1.0f + erff(v0 * 0.70710678118f)));
                v1 = tfr(0.5f * v1 * (1.0f + erff(v1 * 0.70710678118f)));
                v2 = tfr(0.5f * v2 * (1.0f + erff(v2 * 0.70710678118f)));
                v3 = tfr(0.5f * v3 * (1.0f + erff(v3 * 0.70710678118f)));
            }
            if (res != nullptr) {
                float2 r0 = *(const float2*)(res + (size_t)row0 * Nn + col);
                float2 r1 = *(const float2*)(res + (size_t)(row0 + 8) * Nn + col);
                v0 += r0.x; v1 += r0.y; v2 += r1.x; v3 += r1.y;
            }
            float2 o0 = {v0, v1}, o1 = {v2, v3};
            *(float2*)(C + (size_t)row0 * Nn + col) = o0;
            *(float2*)(C + (size_t)(row0 + 8) * Nn + col) = o1;
        }
    }
}

// ---------------- Flash attention on tensor cores (tf32 mma.sync + ldmatrix) ----
#define ATP 68   /* smem pitch: rows walk banks by 4 -> conflict-free */

__global__ __launch_bounds__(256, 1) void attn_tc(
    const float* __restrict__ qkv, float* __restrict__ out) {
    __shared__ float KS[64 * ATP];
    __shared__ float VT[64 * ATP];

    int t = threadIdx.x;
    int w = t >> 5, lane = t & 31;
    int g = lane >> 2, c = lane & 3;
    int bh = blockIdx.y;
    int n  = bh >> 4;
    int h  = bh & 15;
    int q0 = blockIdx.x * 128;
    int hcol = h * HDIM;

    // B-operand ldmatrix lane offset (shared by K and VT phases)
    const uint32_t bROff = (uint32_t)(((((lane >> 4) * 8) + (lane & 7)) * ATP
                                      + (((lane >> 3) & 1) * 4)) * 4);
    const uint32_t ksBase = smem_u32(KS) + bROff;
    const uint32_t vtBase = smem_u32(VT) + bROff;

    // ---- Q fragments (once, registers), scaled + tf32-rounded ----
    uint32_t qf[8][4];
    {
        int r0 = q0 + w * 16 + g;
        const float* qp0 = qkv + ((size_t)(r0 * NB + n)) * (3 * EMB) + hcol;
        const float* qp1 = qkv + ((size_t)((r0 + 8) * NB + n)) * (3 * EMB) + hcol;
        #pragma unroll
        for (int kc = 0; kc < 8; kc++) {
            qf[kc][0] = f2tf(qp0[kc * 8 + c] * QSCALE);
            qf[kc][1] = f2tf(qp1[kc * 8 + c] * QSCALE);
            qf[kc][2] = f2tf(qp0[kc * 8 + c + 4] * QSCALE);
            qf[kc][3] = f2tf(qp1[kc * 8 + c + 4] * QSCALE);
        }
    }

    float o_[8][4];
    #pragma unroll
    for (int j = 0; j < 8; j++)
        #pragma unroll
        for (int q = 0; q < 4; q++) o_[j][q] = 0.f;
    float m0 = -1e30f, m1 = -1e30f, l0 = 0.f, l1 = 0.f;

    int srcLo = (lane & ~3) | (c >> 1);
    int srcHi = srcLo + 2;

    for (int kt = 0; kt < L_SEQ / 64; kt++) {
        int k0 = kt * 64;
        __syncthreads();

        // K tile: [key][d]
        #pragma unroll
        for (int i = 0; i < 4; i++) {
            int idx = i * 256 + t;
            int r = idx >> 4, u = idx & 15;
            float4 kv = *(const float4*)(qkv + ((size_t)((k0 + r) * NB + n)) * (3 * EMB)
                                          + EMB + hcol + u * 4);
            *(float4*)&KS[r * ATP + u * 4] = kv;
        }
        // V tile transposed: VT[d][key]
        #pragma unroll
        for (int i = 0; i < 4; i++) {
            int idx = i * 256 + t;
            int u2 = idx & 7, r = (idx >> 3) & 63, half = idx >> 9;
            int dc = (u2 + half * 8) * 4;
            float4 vv = *(const float4*)(qkv + ((size_t)((k0 + r) * NB + n)) * (3 * EMB)
                                          + 2 * EMB + hcol + dc);
            VT[(dc + 0) * ATP + r] = vv.x;
            VT[(dc + 1) * ATP + r] = vv.y;
            VT[(dc + 2) * ATP + r] = vv.z;
            VT[(dc + 3) * ATP + r] = vv.w;
        }
        __syncthreads();

        // ---- scores: S[16q x 64k] via ldmatrix + mma ----
        float s[8][4];
        #pragma unroll
        for (int j = 0; j < 8; j++)
            #pragma unroll
            for (int q = 0; q < 4; q++) s[j][q] = 0.f;
        #pragma unroll
        for (int kc = 0; kc < 8; kc++) {
            #pragma unroll
            for (int jp = 0; jp < 4; jp++) {
                uint32_t bf[4];
                ldsm4(bf, ksBase + (uint32_t)(jp * 16 * ATP * 4) + (uint32_t)(kc * 32));
                mma_tf32(s[2 * jp],     qf[kc], &bf[0]);
                mma_tf32(s[2 * jp + 1], qf[kc], &bf[2]);
            }
        }

        // ---- online softmax (registers + quad shfl) ----
        float mx0 = s[0][0], mx1 = s[0][2];
        #pragma unroll
        for (int j = 0; j < 8; j++) {
            mx0 = fmaxf(mx0, fmaxf(s[j][0], s[j][1]));
            mx1 = fmaxf(mx1, fmaxf(s[j][2], s[j][3]));
        }
        mx0 = fmaxf(mx0, __shfl_xor_sync(0xffffffffu, mx0, 1));
        mx0 = fmaxf(mx0, __shfl_xor_sync(0xffffffffu, mx0, 2));
        mx1 = fmaxf(mx1, __shfl_xor_sync(0xffffffffu, mx1, 1));
        mx1 = fmaxf(mx1, __shfl_xor_sync(0xffffffffu, mx1, 2));
        float nm0 = fmaxf(m0, mx0), nm1 = fmaxf(m1, mx1);
        float corr0 = fexp(m0 - nm0), corr1 = fexp(m1 - nm1);
        m0 = nm0; m1 = nm1;
        float sum0 = 0.f, sum1 = 0.f;
        #pragma unroll
        for (int j = 0; j < 8; j++) {
            s[j][0] = fexp(s[j][0] - m0);
            s[j][1] = fexp(s[j][1] - m0);
            s[j][2] = fexp(s[j][2] - m1);
            s[j][3] = fexp(s[j][3] - m1);
            sum0 += s[j][0] + s[j][1];
            sum1 += s[j][2] + s[j][3];
        }
        sum0 += __shfl_xor_sync(0xffffffffu, sum0, 1);
        sum0 += __shfl_xor_sync(0xffffffffu, sum0, 2);
        sum1 += __shfl_xor_sync(0xffffffffu, sum1, 1);
        sum1 += __shfl_xor_sync(0xffffffffu, sum1, 2);
        l0 = l0 * corr0 + sum0;
        l1 = l1 * corr1 + sum1;
        #pragma unroll
        for (int j = 0; j < 8; j++) {
            o_[j][0] *= corr0; o_[j][1] *= corr0;
            o_[j][2] *= corr1; o_[j][3] *= corr1;
        }

        // ---- PV: layout-convert P via shfl, ldmatrix VT, mma ----
        #pragma unroll
        for (int kc = 0; kc < 8; kc++) {
            float t00 = __shfl_sync(0xffffffffu, s[kc][0], srcLo);
            float t01 = __shfl_sync(0xffffffffu, s[kc][1], srcLo);
            float t10 = __shfl_sync(0xffffffffu, s[kc][2], srcLo);
            float t11 = __shfl_sync(0xffffffffu, s[kc][3], srcLo);
            float t20 = __shfl_sync(0xffffffffu, s[kc][0], srcHi);
            float t21 = __shfl_sync(0xffffffffu, s[kc][1], srcHi);
            float t30 = __shfl_sync(0xffffffffu, s[kc][2], srcHi);
            float t31 = __shfl_sync(0xffffffffu, s[kc][3], srcHi);
            uint32_t pa[4];
            pa[0] = f2tf((c & 1) ? t01 : t00);
            pa[1] = f2tf((c & 1) ? t11 : t10);
            pa[2] = f2tf((c & 1) ? t21 : t20);
            pa[3] = f2tf((c & 1) ? t31 : t30);
            #pragma unroll
            for (int jp = 0; jp < 4; jp++) {
                uint32_t bf[4];
                ldsm4(bf, vtBase + (uint32_t)(jp * 16 * ATP * 4) + (uint32_t)(kc * 32));
                mma_tf32(o_[2 * jp],     pa, &bf[0]);
                mma_tf32(o_[2 * jp + 1], pa, &bf[2]);
            }
        }
    }

    // ---- write output (rounded: feeds out-proj GEMM as A operand) ----
    float inv0 = 1.0f / l0, inv1 = 1.0f / l1;
    int r0 = q0 + w * 16 + g;
    float* out0 = out + ((size_t)(r0 * NB + n)) * EMB + hcol;
    float* out1 = out + ((size_t)((r0 + 8) * NB + n)) * EMB + hcol;
    #pragma unroll
    for (int j = 0; j < 8; j++) {
        int col = 8 * j + 2 * c;
        float2 a = {tfr(o_[j][0] * inv0), tfr(o_[j][1] * inv0)};
        float2 b = {tfr(o_[j][2] * inv1), tfr(o_[j][3] * inv1)};
        *(float2*)(out0 + col) = a;
        *(float2*)(out1 + col) = b;
    }
}

// ---------------- driver --------------------------------------------------------
extern "C" void kernel_launch(void* const* d_in, const int* in_sizes, int n_in,
                              void* d_out, int out_size) {
    const float* x         = (const float*)d_in[0];
    const float* ln1_w     = (const float*)d_in[1];
    const float* ln1_b     = (const float*)d_in[2];
    const float* in_proj_w = (const float*)d_in[3];
    const float* in_proj_b = (const float*)d_in[4];
    const float* out_w     = (const float*)d_in[5];
    const float* out_b     = (const float*)d_in[6];
    const float* ln2_w     = (const float*)d_in[7];
    const float* ln2_b     = (const float*)d_in[8];
    const float* fc_w      = (const float*)d_in[9];
    const float* fc_b      = (const float*)d_in[10];
    const float* proj_w    = (const float*)d_in[11];
    const float* proj_b    = (const float*)d_in[12];
    float* out = (float*)d_out;

    float *y, *qkv, *o, *x1, *hbuf;
    cudaGetSymbolAddress((void**)&y,    g_y);
    cudaGetSymbolAddress((void**)&qkv,  g_qkv);
    cudaGetSymbolAddress((void**)&o,    g_o);
    cudaGetSymbolAddress((void**)&x1,   g_x1);
    cudaGetSymbolAddress((void**)&hbuf, g_h);

    static bool attr_done = false;
    if (!attr_done) {
        cudaFuncSetAttribute(gemm_tc<0>, cudaFuncAttributeMaxDynamicSharedMemorySize, G_SMEM_BYTES);
        cudaFuncSetAttribute(gemm_tc<1>, cudaFuncAttributeMaxDynamicSharedMemorySize, G_SMEM_BYTES);
        attr_done = true;
    }

    // 1. y = LN1(x)
    ln_kernel<<<ROWS, 256>>>(x, ln1_w, ln1_b, y);
    // 2. qkv = y @ in_proj_w^T + in_proj_b
    gemm_tc<0><<<dim3(3 * EMB / GBN, ROWS / GBM), 256, G_SMEM_BYTES>>>(
        y, in_proj_w, in_proj_b, nullptr, qkv, ROWS, 3 * EMB, EMB);
    // 3. o = attention(qkv)
    attn_tc<<<dim3(L_SEQ / 128, NB * NHEAD), 256>>>(qkv, o);
    // 4. x1 = x + o @ out_w^T + out_b
    gemm_tc<0><<<dim3(EMB / GBN, ROWS / GBM), 256, G_SMEM_BYTES>>>(
        o, out_w, out_b, x, x1, ROWS, EMB, EMB);
    // 5. y = LN2(x1)
    ln_kernel<<<ROWS, 256>>>(x1, ln2_w, ln2_b, y);
    // 6. h = GELU(y @ fc_w^T + fc_b)  (h rounded in epilogue)
    gemm_tc<1><<<dim3(FFN / GBN, ROWS / GBM), 256, G_SMEM_BYTES>>>(
        y, fc_w, fc_b, nullptr, hbuf, ROWS, FFN, EMB);
    // 7. out = x1 + h @ proj_w^T + proj_b
    gemm_tc<0><<<dim3(EMB / GBN, ROWS / GBM), 256, G_SMEM_BYTES>>>(
        hbuf, proj_w, proj_b, x1, out, ROWS, EMB, FFN);
}

// round 7
// speedup vs baseline: 9.2124x; 1.6901x over previous
#include <cuda_runtime.h>
#include <cuda_fp16.h>
#include <math.h>
#include <stdint.h>

#define L_SEQ 2048
#define NB    2
#define EMB   1024
#define NHEAD 16
#define HDIM  64
#define ROWS  (L_SEQ * NB)   /* 4096 */
#define FFN   (4 * EMB)      /* 4096 */
#define MM    (1024 * 1024)

// ---------------- scratch (no allocation; __device__ globals) -------------------
__device__ __half g_yh[(size_t)ROWS * EMB];
__device__ __half g_qkvh[(size_t)ROWS * 3 * EMB];
__device__ __half g_oh[(size_t)ROWS * EMB];
__device__ float  g_x1[(size_t)ROWS * EMB];
__device__ __half g_hh[(size_t)ROWS * FFN];
__device__ __half g_wh[(size_t)12 * MM];     // fp16 weights: inproj|out|fc|proj

// ---------------- helpers -------------------------------------------------------
__device__ __forceinline__ uint32_t smem_u32(const void* p) {
    uint32_t a;
    asm("{ .reg .u64 t; cvta.to.shared.u64 t, %1; cvt.u32.u64 %0, t; }" : "=r"(a) : "l"(p));
    return a;
}
__device__ __forceinline__ void cp16(uint32_t s, const void* g) {
    asm volatile("cp.async.cg.shared.global [%0], [%1], 16;" :: "r"(s), "l"(g) : "memory");
}
#define CP_COMMIT() asm volatile("cp.async.commit_group;" ::: "memory")

__device__ __forceinline__ void mma_fp16(float* d, const uint32_t* a, const uint32_t* b) {
    asm volatile(
        "mma.sync.aligned.m16n8k16.row.col.f32.f16.f16.f32 "
        "{%0,%1,%2,%3}, {%4,%5,%6,%7}, {%8,%9}, {%0,%1,%2,%3};"
        : "+f"(d[0]), "+f"(d[1]), "+f"(d[2]), "+f"(d[3])
        : "r"(a[0]), "r"(a[1]), "r"(a[2]), "r"(a[3]), "r"(b[0]), "r"(b[1]));
}
__device__ __forceinline__ void ldsm4(uint32_t* r, uint32_t addr) {
    asm volatile("ldmatrix.sync.aligned.m8n8.x4.shared.b16 {%0,%1,%2,%3}, [%4];"
                 : "=r"(r[0]), "=r"(r[1]), "=r"(r[2]), "=r"(r[3]) : "r"(addr));
}
__device__ __forceinline__ uint32_t packh2(float a, float b) {
    __half2 h = __floats2half2_rn(a, b);
    return *(uint32_t*)&h;
}

// fast exp: FFMA-only, rel err ~1e-7
__device__ __forceinline__ float fexp(float x) {
    x = fmaxf(x, -80.0f);
    float t = x * 1.4426950408889634f;
    float r = t + 12582912.0f;
    float i = r - 12582912.0f;
    float f = t - i;
    float p = 1.3333558146428443e-3f;
    p = fmaf(p, f, 9.6181291076284772e-3f);
    p = fmaf(p, f, 5.5504108664821580e-2f);
    p = fmaf(p, f, 2.4022650695910072e-1f);
    p = fmaf(p, f, 6.9314718055994531e-1f);
    p = fmaf(p, f, 1.0f);
    return p * __int_as_float(((int)i + 127) << 23);
}

// ---------------- fp32 -> fp16 conversion (weights, once per launch) ------------
__global__ void cvt_half(const float* __restrict__ src, __half* __restrict__ dst, int n4) {
    int i = blockIdx.x * blockDim.x + threadIdx.x;
    if (i < n4) {
        float4 v = ((const float4*)src)[i];
        uint2 u = {packh2(v.x, v.y), packh2(v.z, v.w)};
        ((uint2*)dst)[i] = u;
    }
}

// ---------------- LayerNorm: fp32 in -> fp16 out --------------------------------
__global__ void ln_kernel(const float* __restrict__ x,
                          const float* __restrict__ w,
                          const float* __restrict__ b,
                          __half* __restrict__ y) {
    int row = blockIdx.x;
    int t = threadIdx.x;
    const float4 v = ((const float4*)(x + (size_t)row * EMB))[t];
    float s  = v.x + v.y + v.z + v.w;
    float sq = v.x * v.x + v.y * v.y + v.z * v.z + v.w * v.w;
    #pragma unroll
    for (int o = 16; o; o >>= 1) {
        s  += __shfl_xor_sync(0xffffffffu, s, o);
        sq += __shfl_xor_sync(0xffffffffu, sq, o);
    }
    __shared__ float ss[8], ssq[8];
    int wid = t >> 5, lid = t & 31;
    if (lid == 0) { ss[wid] = s; ssq[wid] = sq; }
    __syncthreads();
    if (t == 0) {
        float a = 0.f, c = 0.f;
        #pragma unroll
        for (int i = 0; i < 8; i++) { a += ss[i]; c += ssq[i]; }
        ss[0] = a; ssq[0] = c;
    }
    __syncthreads();
    float mu  = ss[0] * (1.0f / EMB);
    float var = ssq[0] * (1.0f / EMB) - mu * mu;
    float rs  = rsqrtf(var + 1e-5f);
    const float4 wv = ((const float4*)w)[t];
    const float4 bv = ((const float4*)b)[t];
    uint2 o;
    o.x = packh2((v.x - mu) * rs * wv.x + bv.x, (v.y - mu) * rs * wv.y + bv.y);
    o.y = packh2((v.z - mu) * rs * wv.z + bv.z, (v.w - mu) * rs * wv.w + bv.w);
    ((uint2*)(y + (size_t)row * EMB))[t] = o;
}

// ---------------- fp16 mma GEMM: C[M,Nn] = A[M,K]*B[Nn,K]^T ---------------------
// Block 128x128, BK=32 halves, 8 warps 2x4 (warp tile 64x32), 3-stage cp.async,
// one __syncthreads per k-tile. A,B fp16; accum + epilogue fp32.
#define GBM 128
#define GBN 128
#define GBK 32
#define GP  40                                  /* pitch in halves (80B) */
#define STAGE_H (2 * GBM * GP)                  /* halves per stage (A+B) */
#define NSTAGE 3
#define G_SMEM_BYTES (NSTAGE * STAGE_H * 2)     /* 61440 B */

template <int ACT, int OHALF>
__global__ __launch_bounds__(256, 2)
void gemm_fp16(const __half* __restrict__ A, const __half* __restrict__ B,
               const float* __restrict__ bias, const float* __restrict__ res,
               void* __restrict__ Cout, int M, int Nn, int K) {
    extern __shared__ char smc[];
    uint32_t smemBase = smem_u32(smc);
    int t = threadIdx.x;
    int w = t >> 5, lane = t & 31;
    int g = lane >> 2, c = lane & 3;
    int wm = w & 1, wn = w >> 1;
    int m0 = blockIdx.y * GBM;
    int n0 = blockIdx.x * GBN;
    int KT = K / GBK;

    const __half* Ab = A + (size_t)m0 * K;
    const __half* Bb = B + (size_t)n0 * K;

    // ldmatrix lane-address roles
    const uint32_t aOff = (uint32_t)((wm * 64 + (lane & 15)) * 80 + (lane >> 4) * 16);
    const uint32_t bOff = (uint32_t)(GBM * GP * 2)
                        + (uint32_t)((wn * 32 + (lane & 7) + ((lane >> 4) * 8)) * 80
                                     + ((lane >> 3) & 1) * 16);

    float d[4][4][4];
    #pragma unroll
    for (int i = 0; i < 4; i++)
        #pragma unroll
        for (int j = 0; j < 4; j++)
            #pragma unroll
            for (int q = 0; q < 4; q++) d[i][j][q] = 0.f;

    auto load_stage = [&](int s, int k0) {
        uint32_t aS = smemBase + (uint32_t)(s * STAGE_H * 2);
        uint32_t bS = aS + GBM * GP * 2;
        #pragma unroll
        for (int i = 0; i < 2; i++) {
            int ch = t + i * 256;                // 0..511
            int row = ch >> 2, cc = ch & 3;      // 4 x 16B chunks per row
            cp16(aS + (uint32_t)(row * 80 + cc * 16), Ab + (size_t)row * K + k0 + cc * 8);
            cp16(bS + (uint32_t)(row * 80 + cc * 16), Bb + (size_t)row * K + k0 + cc * 8);
        }
    };

    load_stage(0, 0); CP_COMMIT();
    if (KT > 1) load_stage(1, GBK);
    CP_COMMIT();

    for (int kt = 0; kt < KT; kt++) {
        asm volatile("cp.async.wait_group 1;" ::: "memory");
        __syncthreads();
        if (kt + 2 < KT) load_stage((kt + 2) % NSTAGE, (kt + 2) * GBK);
        CP_COMMIT();

        uint32_t stBase = smemBase + (uint32_t)((kt % NSTAGE) * STAGE_H * 2);
        uint32_t aAddr = stBase + aOff;
        uint32_t bAddr = stBase + bOff;

        #pragma unroll
        for (int kk = 0; kk < 2; kk++) {         // 2 x k16 = BK 32
            uint32_t kb = (uint32_t)(kk * 32);   // 16 halves = 32B
            uint32_t a[4][4], b[2][4];
            #pragma unroll
            for (int i = 0; i < 4; i++)
                ldsm4(a[i], aAddr + (uint32_t)(i * 16 * 80) + kb);
            #pragma unroll
            for (int jp = 0; jp < 2; jp++)
                ldsm4(b[jp], bAddr + (uint32_t)(jp * 16 * 80) + kb);
            #pragma unroll
            for (int i = 0; i < 4; i++)
                #pragma unroll
                for (int j = 0; j < 4; j++)
                    mma_fp16(d[i][j], a[i], &b[j >> 1][(j & 1) * 2]);
        }
    }

    // ---- epilogue ----
    #pragma unroll
    for (int i = 0; i < 4; i++) {
        int row0 = m0 + wm * 64 + i * 16 + g;
        #pragma unroll
        for (int j = 0; j < 4; j++) {
            int col = n0 + wn * 32 + j * 8 + 2 * c;
            float2 bv = *(const float2*)(bias + col);
            float v0 = d[i][j][0] + bv.x;
            float v1 = d[i][j][1] + bv.y;
            float v2 = d[i][j][2] + bv.x;
            float v3 = d[i][j][3] + bv.y;
            if (ACT == 1) {
                v0 = 0.5f * v0 * (1.0f + erff(v0 * 0.70710678118f));
                v1 = 0.5f * v1 * (1.0f + erff(v1 * 0.70710678118f));
                v2 = 0.5f * v2 * (1.0f + erff(v2 * 0.70710678118f));
                v3 = 0.5f * v3 * (1.0f + erff(v3 * 0.70710678118f));
            }
            if (OHALF) {
                __half* Ch = (__half*)Cout;
                *(uint32_t*)(Ch + (size_t)row0 * Nn + col)       = packh2(v0, v1);
                *(uint32_t*)(Ch + (size_t)(row0 + 8) * Nn + col) = packh2(v2, v3);
            } else {
                if (res != nullptr) {
                    float2 r0 = *(const float2*)(res + (size_t)row0 * Nn + col);
                    float2 r1 = *(const float2*)(res + (size_t)(row0 + 8) * Nn + col);
                    v0 += r0.x; v1 += r0.y; v2 += r1.x; v3 += r1.y;
                }
                float* Cf = (float*)Cout;
                float2 o0 = {v0, v1}, o1 = {v2, v3};
                *(float2*)(Cf + (size_t)row0 * Nn + col) = o0;
                *(float2*)(Cf + (size_t)(row0 + 8) * Nn + col) = o1;
            }
        }
    }
}

// ---------------- Flash attention, all-fp16 operands ----------------------------
// grid (L/128, NB*NHEAD), 256 thr = 8 warps x 16 q-rows. qkv in fp16.
// fp16 trick: score d-frags pack directly into PV a-frags (no shuffles).
#define ATPH 72   /* pitch in halves: 144B, bank-stride 4 -> conflict-free */

__global__ __launch_bounds__(256, 2) void attn_fp16(
    const __half* __restrict__ qkv, __half* __restrict__ out) {
    __shared__ __half KS[64 * ATPH];
    __shared__ __half VT[64 * ATPH];

    int t = threadIdx.x;
    int w = t >> 5, lane = t & 31;
    int g = lane >> 2, c = lane & 3;
    int bh = blockIdx.y;
    int n  = bh >> 4;
    int h  = bh & 15;
    int q0 = blockIdx.x * 128;
    int hcol = h * HDIM;

    const uint32_t bROff = (uint32_t)(((lane & 7) + ((lane >> 4) * 8)) * 144
                                      + ((lane >> 3) & 1) * 16);
    const uint32_t ksBase = smem_u32(KS) + bROff;
    const uint32_t vtBase = smem_u32(VT) + bROff;

    // ---- Q fragments (registers, packed half2, scaled by 1/64 exactly) ----
    uint32_t qf[4][4];
    {
        int r0 = q0 + w * 16 + g;
        const __half* qp0 = qkv + ((size_t)(r0 * NB + n)) * (3 * EMB) + hcol;
        const __half* qp1 = qkv + ((size_t)((r0 + 8) * NB + n)) * (3 * EMB) + hcol;
        __half2 qsc = __half2half2(__float2half_rn(1.0f / 64.0f));
        #pragma unroll
        for (int kk = 0; kk < 4; kk++) {
            __half2 h0 = __hmul2(*(const __half2*)(qp0 + kk * 16 + 2 * c), qsc);
            __half2 h1 = __hmul2(*(const __half2*)(qp1 + kk * 16 + 2 * c), qsc);
            __half2 h2 = __hmul2(*(const __half2*)(qp0 + kk * 16 + 8 + 2 * c), qsc);
            __half2 h3 = __hmul2(*(const __half2*)(qp1 + kk * 16 + 8 + 2 * c), qsc);
            qf[kk][0] = *(uint32_t*)&h0; qf[kk][1] = *(uint32_t*)&h1;
            qf[kk][2] = *(uint32_t*)&h2; qf[kk][3] = *(uint32_t*)&h3;
        }
    }

    float o_[8][4];
    #pragma unroll
    for (int j = 0; j < 8; j++)
        #pragma unroll
        for (int q = 0; q < 4; q++) o_[j][q] = 0.f;
    float m0 = -1e30f, m1 = -1e30f, l0 = 0.f, l1 = 0.f;

    for (int kt = 0; kt < L_SEQ / 64; kt++) {
        int k0 = kt * 64;
        __syncthreads();

        // K tile: cp.async straight copy (fp16 already)
        #pragma unroll
        for (int i = 0; i < 2; i++) {
            int idx = t + i * 256;               // 0..511
            int r = idx >> 3, cc = idx & 7;
            cp16(smem_u32(KS) + (uint32_t)(r * 144 + cc * 16),
                 qkv + ((size_t)((k0 + r) * NB + n)) * (3 * EMB) + EMB + hcol + cc * 8);
        }
        // V tile transposed: VT[d][key] (manual 16B load + 8 scalar half stores)
        #pragma unroll
        for (int i = 0; i < 2; i++) {
            int idx = t + i * 256;
            int r = idx & 63, dch = idx >> 6;    // dch 0..7 => d-dims dch*8..+7
            uint4 raw = *(const uint4*)(qkv + ((size_t)((k0 + r) * NB + n)) * (3 * EMB)
                                         + 2 * EMB + hcol + dch * 8);
            const __half* hp = (const __half*)&raw;
            #pragma unroll
            for (int u = 0; u < 8; u++)
                VT[(dch * 8 + u) * ATPH + r] = hp[u];
        }
        CP_COMMIT();
        asm volatile("cp.async.wait_group 0;" ::: "memory");
        __syncthreads();

        // ---- scores: S[16q x 64k] ----
        float s[8][4];
        #pragma unroll
        for (int j = 0; j < 8; j++)
            #pragma unroll
            for (int q = 0; q < 4; q++) s[j][q] = 0.f;
        #pragma unroll
        for (int kk = 0; kk < 4; kk++) {
            #pragma unroll
            for (int jp = 0; jp < 4; jp++) {
                uint32_t bf[4];
                ldsm4(bf, ksBase + (uint32_t)(jp * 16 * 144) + (uint32_t)(kk * 32));
                mma_fp16(s[2 * jp],     qf[kk], &bf[0]);
                mma_fp16(s[2 * jp + 1], qf[kk], &bf[2]);
            }
        }

        // ---- online softmax (registers + quad shfl) ----
        float mx0 = s[0][0], mx1 = s[0][2];
        #pragma unroll
        for (int j = 0; j < 8; j++) {
            mx0 = fmaxf(mx0, fmaxf(s[j][0], s[j][1]));
            mx1 = fmaxf(mx1, fmaxf(s[j][2], s[j][3]));
        }
        mx0 = fmaxf(mx0, __shfl_xor_sync(0xffffffffu, mx0, 1));
        mx0 = fmaxf(mx0, __shfl_xor_sync(0xffffffffu, mx0, 2));
        mx1 = fmaxf(mx1, __shfl_xor_sync(0xffffffffu, mx1, 1));
        mx1 = fmaxf(mx1, __shfl_xor_sync(0xffffffffu, mx1, 2));
        float nm0 = fmaxf(m0, mx0), nm1 = fmaxf(m1, mx1);
        float corr0 = fexp(m0 - nm0), corr1 = fexp(m1 - nm1);
        m0 = nm0; m1 = nm1;
        float sum0 = 0.f, sum1 = 0.f;
        #pragma unroll
        for (int j = 0; j < 8; j++) {
            s[j][0] = fexp(s[j][0] - m0);
            s[j][1] = fexp(s[j][1] - m0);
            s[j][2] = fexp(s[j][2] - m1);
            s[j][3] = fexp(s[j][3] - m1);
            sum0 += s[j][0] + s[j][1];
            sum1 += s[j][2] + s[j][3];
        }
        sum0 += __shfl_xor_sync(0xffffffffu, sum0, 1);
        sum0 += __shfl_xor_sync(0xffffffffu, sum0, 2);
        sum1 += __shfl_xor_sync(0xffffffffu, sum1, 1);
        sum1 += __shfl_xor_sync(0xffffffffu, sum1, 2);
        l0 = l0 * corr0 + sum0;
        l1 = l1 * corr1 + sum1;
        #pragma unroll
        for (int j = 0; j < 8; j++) {
            o_[j][0] *= corr0; o_[j][1] *= corr0;
            o_[j][2] *= corr1; o_[j][3] *= corr1;
        }

        // ---- PV: d-frag -> a-frag pack (no shuffles), mma against VT ----
        #pragma unroll
        for (int u = 0; u < 4; u++) {            // k16 block = keys 16u..16u+15
            uint32_t pa[4];
            pa[0] = packh2(s[2 * u][0],     s[2 * u][1]);
            pa[1] = packh2(s[2 * u][2],     s[2 * u][3]);
            pa[2] = packh2(s[2 * u + 1][0], s[2 * u + 1][1]);
            pa[3] = packh2(s[2 * u + 1][2], s[2 * u + 1][3]);
            #pragma unroll
            for (int jp = 0; jp < 4; jp++) {
                uint32_t bf[4];
                ldsm4(bf, vtBase + (uint32_t)(jp * 16 * 144) + (uint32_t)(u * 32));
                mma_fp16(o_[2 * jp],     pa, &bf[0]);
                mma_fp16(o_[2 * jp + 1], pa, &bf[2]);
            }
        }
    }

    // ---- write output (fp16, feeds out-proj GEMM) ----
    float inv0 = 1.0f / l0, inv1 = 1.0f / l1;
    int r0 = q0 + w * 16 + g;
    __half* out0 = out + ((size_t)(r0 * NB + n)) * EMB + hcol;
    __half* out1 = out + ((size_t)((r0 + 8) * NB + n)) * EMB + hcol;
    #pragma unroll
    for (int j = 0; j < 8; j++) {
        int col = 8 * j + 2 * c;
        *(uint32_t*)(out0 + col) = packh2(o_[j][0] * inv0, o_[j][1] * inv0);
        *(uint32_t*)(out1 + col) = packh2(o_[j][2] * inv1, o_[j][3] * inv1);
    }
}

// ---------------- driver --------------------------------------------------------
extern "C" void kernel_launch(void* const* d_in, const int* in_sizes, int n_in,
                              void* d_out, int out_size) {
    const float* x         = (const float*)d_in[0];
    const float* ln1_w     = (const float*)d_in[1];
    const float* ln1_b     = (const float*)d_in[2];
    const float* in_proj_w = (const float*)d_in[3];
    const float* in_proj_b = (const float*)d_in[4];
    const float* out_w     = (const float*)d_in[5];
    const float* out_b     = (const float*)d_in[6];
    const float* ln2_w     = (const float*)d_in[7];
    const float* ln2_b     = (const float*)d_in[8];
    const float* fc_w      = (const float*)d_in[9];
    const float* fc_b      = (const float*)d_in[10];
    const float* proj_w    = (const float*)d_in[11];
    const float* proj_b    = (const float*)d_in[12];
    float* out = (float*)d_out;

    __half *yh, *qkvh, *oh, *hh, *wh;
    float *x1;
    cudaGetSymbolAddress((void**)&yh,   g_yh);
    cudaGetSymbolAddress((void**)&qkvh, g_qkvh);
    cudaGetSymbolAddress((void**)&oh,   g_oh);
    cudaGetSymbolAddress((void**)&x1,   g_x1);
    cudaGetSymbolAddress((void**)&hh,   g_hh);
    cudaGetSymbolAddress((void**)&wh,   g_wh);
    __half* wh_inproj = wh;
    __half* wh_out    = wh + (size_t)3 * MM;
    __half* wh_fc     = wh + (size_t)4 * MM;
    __half* wh_proj   = wh + (size_t)8 * MM;

    static bool attr_done = false;
    if (!attr_done) {
        cudaFuncSetAttribute(gemm_fp16<0, 0>, cudaFuncAttributeMaxDynamicSharedMemorySize, G_SMEM_BYTES);
        cudaFuncSetAttribute(gemm_fp16<0, 1>, cudaFuncAttributeMaxDynamicSharedMemorySize, G_SMEM_BYTES);
        cudaFuncSetAttribute(gemm_fp16<1, 1>, cudaFuncAttributeMaxDynamicSharedMemorySize, G_SMEM_BYTES);
        attr_done = true;
    }

    // 0. convert weights to fp16
    cvt_half<<<(3 * MM / 4 + 255) / 256, 256>>>(in_proj_w, wh_inproj, 3 * MM / 4);
    cvt_half<<<(MM / 4 + 255) / 256, 256>>>(out_w, wh_out, MM / 4);
    cvt_half<<<(4 * MM / 4 + 255) / 256, 256>>>(fc_w, wh_fc, MM);
    cvt_half<<<(4 * MM / 4 + 255) / 256, 256>>>(proj_w, wh_proj, MM);

    // 1. y = LN1(x) -> fp16
    ln_kernel<<<ROWS, 256>>>(x, ln1_w, ln1_b, yh);
    // 2. qkv = y @ in_proj_w^T + b -> fp16
    gemm_fp16<0, 1><<<dim3(3 * EMB / GBN, ROWS / GBM), 256, G_SMEM_BYTES>>>(
        yh, wh_inproj, in_proj_b, nullptr, qkvh, ROWS, 3 * EMB, EMB);
    // 3. o = attention(qkv) -> fp16
    attn_fp16<<<dim3(L_SEQ / 128, NB * NHEAD), 256>>>(qkvh, oh);
    // 4. x1 = x + o @ out_w^T + b  (fp32)
    gemm_fp16<0, 0><<<dim3(EMB / GBN, ROWS / GBM), 256, G_SMEM_BYTES>>>(
        oh, wh_out, out_b, x, x1, ROWS, EMB, EMB);
    // 5. y = LN2(x1) -> fp16
    ln_kernel<<<ROWS, 256>>>(x1, ln2_w, ln2_b, yh);
    // 6. h = GELU(y @ fc_w^T + b) -> fp16
    gemm_fp16<1, 1><<<dim3(FFN / GBN, ROWS / GBM), 256, G_SMEM_BYTES>>>(
        yh, wh_fc, fc_b, nullptr, hh, ROWS, FFN, EMB);
    // 7. out = x1 + h @ proj_w^T + b  (fp32)
    gemm_fp16<0, 0><<<dim3(EMB / GBN, ROWS / GBM), 256, G_SMEM_BYTES>>>(
        hh, wh_proj, proj_b, x1, out, ROWS, EMB, FFN);
}

// round 8
// speedup vs baseline: 9.6002x; 1.0421x over previous
#include <cuda_runtime.h>
#include <cuda_fp16.h>
#include <math.h>
#include <stdint.h>

#define L_SEQ 2048
#define NB    2
#define EMB   1024
#define NHEAD 16
#define HDIM  64
#define ROWS  (L_SEQ * NB)   /* 4096 */
#define FFN   (4 * EMB)      /* 4096 */
#define MM    (1024 * 1024)

// ---------------- scratch (no allocation; __device__ globals) -------------------
__device__ __half g_yh[(size_t)ROWS * EMB];
__device__ __half g_qkvh[(size_t)ROWS * 3 * EMB];
__device__ __half g_oh[(size_t)ROWS * EMB];
__device__ float  g_x1[(size_t)ROWS * EMB];
__device__ __half g_hh[(size_t)ROWS * FFN];
__device__ __half g_wh[(size_t)12 * MM];     // fp16 weights: inproj|out|fc|proj

// ---------------- helpers -------------------------------------------------------
__device__ __forceinline__ uint32_t smem_u32(const void* p) {
    uint32_t a;
    asm("{ .reg .u64 t; cvta.to.shared.u64 t, %1; cvt.u32.u64 %0, t; }" : "=r"(a) : "l"(p));
    return a;
}
__device__ __forceinline__ void cp16(uint32_t s, const void* g) {
    asm volatile("cp.async.cg.shared.global [%0], [%1], 16;" :: "r"(s), "l"(g) : "memory");
}
#define CP_COMMIT() asm volatile("cp.async.commit_group;" ::: "memory")

__device__ __forceinline__ void mma_fp16(float* d, const uint32_t* a, const uint32_t* b) {
    asm volatile(
        "mma.sync.aligned.m16n8k16.row.col.f32.f16.f16.f32 "
        "{%0,%1,%2,%3}, {%4,%5,%6,%7}, {%8,%9}, {%0,%1,%2,%3};"
        : "+f"(d[0]), "+f"(d[1]), "+f"(d[2]), "+f"(d[3])
        : "r"(a[0]), "r"(a[1]), "r"(a[2]), "r"(a[3]), "r"(b[0]), "r"(b[1]));
}
__device__ __forceinline__ void ldsm4(uint32_t* r, uint32_t addr) {
    asm volatile("ldmatrix.sync.aligned.m8n8.x4.shared.b16 {%0,%1,%2,%3}, [%4];"
                 : "=r"(r[0]), "=r"(r[1]), "=r"(r[2]), "=r"(r[3]) : "r"(addr));
}
__device__ __forceinline__ void ldsm4t(uint32_t* r, uint32_t addr) {
    asm volatile("ldmatrix.sync.aligned.m8n8.x4.trans.shared.b16 {%0,%1,%2,%3}, [%4];"
                 : "=r"(r[0]), "=r"(r[1]), "=r"(r[2]), "=r"(r[3]) : "r"(addr));
}
__device__ __forceinline__ uint32_t packh2(float a, float b) {
    __half2 h = __floats2half2_rn(a, b);
    return *(uint32_t*)&h;
}

// fast exp: FFMA-only, rel err ~1e-7
__device__ __forceinline__ float fexp(float x) {
    x = fmaxf(x, -80.0f);
    float t = x * 1.4426950408889634f;
    float r = t + 12582912.0f;
    float i = r - 12582912.0f;
    float f = t - i;
    float p = 1.3333558146428443e-3f;
    p = fmaf(p, f, 9.6181291076284772e-3f);
    p = fmaf(p, f, 5.5504108664821580e-2f);
    p = fmaf(p, f, 2.4022650695910072e-1f);
    p = fmaf(p, f, 6.9314718055994531e-1f);
    p = fmaf(p, f, 1.0f);
    return p * __int_as_float(((int)i + 127) << 23);
}

// ---------------- fp32 -> fp16 conversion (weights) -----------------------------
__global__ void cvt_half(const float* __restrict__ src, __half* __restrict__ dst, int n4) {
    int i = blockIdx.x * blockDim.x + threadIdx.x;
    if (i < n4) {
        float4 v = ((const float4*)src)[i];
        uint2 u = {packh2(v.x, v.y), packh2(v.z, v.w)};
        ((uint2*)dst)[i] = u;
    }
}

// ---------------- LayerNorm: fp32 in -> fp16 out --------------------------------
__global__ void ln_kernel(const float* __restrict__ x,
                          const float* __restrict__ w,
                          const float* __restrict__ b,
                          __half* __restrict__ y) {
    int row = blockIdx.x;
    int t = threadIdx.x;
    const float4 v = ((const float4*)(x + (size_t)row * EMB))[t];
    float s  = v.x + v.y + v.z + v.w;
    float sq = v.x * v.x + v.y * v.y + v.z * v.z + v.w * v.w;
    #pragma unroll
    for (int o = 16; o; o >>= 1) {
        s  += __shfl_xor_sync(0xffffffffu, s, o);
        sq += __shfl_xor_sync(0xffffffffu, sq, o);
    }
    __shared__ float ss[8], ssq[8];
    int wid = t >> 5, lid = t & 31;
    if (lid == 0) { ss[wid] = s; ssq[wid] = sq; }
    __syncthreads();
    if (t == 0) {
        float a = 0.f, c = 0.f;
        #pragma unroll
        for (int i = 0; i < 8; i++) { a += ss[i]; c += ssq[i]; }
        ss[0] = a; ssq[0] = c;
    }
    __syncthreads();
    float mu  = ss[0] * (1.0f / EMB);
    float var = ssq[0] * (1.0f / EMB) - mu * mu;
    float rs  = rsqrtf(var + 1e-5f);
    const float4 wv = ((const float4*)w)[t];
    const float4 bv = ((const float4*)b)[t];
    uint2 o;
    o.x = packh2((v.x - mu) * rs * wv.x + bv.x, (v.y - mu) * rs * wv.y + bv.y);
    o.y = packh2((v.z - mu) * rs * wv.z + bv.z, (v.w - mu) * rs * wv.w + bv.w);
    ((uint2*)(y + (size_t)row * EMB))[t] = o;
}

// ---------------- fp16 mma GEMM: C[M,Nn] = A[M,K]*B[Nn,K]^T ---------------------
// Block 128x128, BK=32 halves, 8 warps 2x4 (warp tile 64x32), 4-stage cp.async.
#define GBM 128
#define GBN 128
#define GBK 32
#define GP  40                                  /* pitch in halves (80B) */
#define STAGE_H (2 * GBM * GP)
#define NSTAGE 4
#define G_SMEM_BYTES (NSTAGE * STAGE_H * 2)     /* 81920 B */

template <int ACT, int OHALF>
__global__ __launch_bounds__(256, 2)
void gemm_fp16(const __half* __restrict__ A, const __half* __restrict__ B,
               const float* __restrict__ bias, const float* __restrict__ res,
               void* __restrict__ Cout, int M, int Nn, int K) {
    extern __shared__ char smc[];
    uint32_t smemBase = smem_u32(smc);
    int t = threadIdx.x;
    int w = t >> 5, lane = t & 31;
    int g = lane >> 2, c = lane & 3;
    int wm = w & 1, wn = w >> 1;
    int m0 = blockIdx.y * GBM;
    int n0 = blockIdx.x * GBN;
    int KT = K / GBK;

    const __half* Ab = A + (size_t)m0 * K;
    const __half* Bb = B + (size_t)n0 * K;

    const uint32_t aOff = (uint32_t)((wm * 64 + (lane & 15)) * 80 + (lane >> 4) * 16);
    const uint32_t bOff = (uint32_t)(GBM * GP * 2)
                        + (uint32_t)((wn * 32 + (lane & 7) + ((lane >> 4) * 8)) * 80
                                     + ((lane >> 3) & 1) * 16);

    float d[4][4][4];
    #pragma unroll
    for (int i = 0; i < 4; i++)
        #pragma unroll
        for (int j = 0; j < 4; j++)
            #pragma unroll
            for (int q = 0; q < 4; q++) d[i][j][q] = 0.f;

    auto load_stage = [&](int s, int k0) {
        uint32_t aS = smemBase + (uint32_t)(s * STAGE_H * 2);
        uint32_t bS = aS + GBM * GP * 2;
        #pragma unroll
        for (int i = 0; i < 2; i++) {
            int ch = t + i * 256;
            int row = ch >> 2, cc = ch & 3;
            cp16(aS + (uint32_t)(row * 80 + cc * 16), Ab + (size_t)row * K + k0 + cc * 8);
            cp16(bS + (uint32_t)(row * 80 + cc * 16), Bb + (size_t)row * K + k0 + cc * 8);
        }
    };

    load_stage(0, 0);       CP_COMMIT();
    load_stage(1, GBK);     CP_COMMIT();
    load_stage(2, 2 * GBK); CP_COMMIT();

    for (int kt = 0; kt < KT; kt++) {
        asm volatile("cp.async.wait_group 2;" ::: "memory");
        __syncthreads();
        if (kt + 3 < KT) load_stage((kt + 3) & 3, (kt + 3) * GBK);
        CP_COMMIT();

        uint32_t stBase = smemBase + (uint32_t)((kt & 3) * STAGE_H * 2);
        uint32_t aAddr = stBase + aOff;
        uint32_t bAddr = stBase + bOff;

        #pragma unroll
        for (int kk = 0; kk < 2; kk++) {
            uint32_t kb = (uint32_t)(kk * 32);
            uint32_t a[4][4], b[2][4];
            #pragma unroll
            for (int i = 0; i < 4; i++)
                ldsm4(a[i], aAddr + (uint32_t)(i * 16 * 80) + kb);
            #pragma unroll
            for (int jp = 0; jp < 2; jp++)
                ldsm4(b[jp], bAddr + (uint32_t)(jp * 16 * 80) + kb);
            #pragma unroll
            for (int i = 0; i < 4; i++)
                #pragma unroll
                for (int j = 0; j < 4; j++)
                    mma_fp16(d[i][j], a[i], &b[j >> 1][(j & 1) * 2]);
        }
    }

    // ---- epilogue ----
    #pragma unroll
    for (int i = 0; i < 4; i++) {
        int row0 = m0 + wm * 64 + i * 16 + g;
        #pragma unroll
        for (int j = 0; j < 4; j++) {
            int col = n0 + wn * 32 + j * 8 + 2 * c;
            float2 bv = *(const float2*)(bias + col);
            float v0 = d[i][j][0] + bv.x;
            float v1 = d[i][j][1] + bv.y;
            float v2 = d[i][j][2] + bv.x;
            float v3 = d[i][j][3] + bv.y;
            if (ACT == 1) {
                v0 = 0.5f * v0 * (1.0f + erff(v0 * 0.70710678118f));
                v1 = 0.5f * v1 * (1.0f + erff(v1 * 0.70710678118f));
                v2 = 0.5f * v2 * (1.0f + erff(v2 * 0.70710678118f));
                v3 = 0.5f * v3 * (1.0f + erff(v3 * 0.70710678118f));
            }
            if (OHALF) {
                __half* Ch = (__half*)Cout;
                *(uint32_t*)(Ch + (size_t)row0 * Nn + col)       = packh2(v0, v1);
                *(uint32_t*)(Ch + (size_t)(row0 + 8) * Nn + col) = packh2(v2, v3);
            } else {
                if (res != nullptr) {
                    float2 r0 = *(const float2*)(res + (size_t)row0 * Nn + col);
                    float2 r1 = *(const float2*)(res + (size_t)(row0 + 8) * Nn + col);
                    v0 += r0.x; v1 += r0.y; v2 += r1.x; v3 += r1.y;
                }
                float* Cf = (float*)Cout;
                float2 o0 = {v0, v1}, o1 = {v2, v3};
                *(float2*)(Cf + (size_t)row0 * Nn + col) = o0;
                *(float2*)(Cf + (size_t)(row0 + 8) * Nn + col) = o1;
            }
        }
    }
}

// ---------------- Flash attention, fp16, 3-stage K/V pipeline, trans-ldmatrix V --
#define ATPB 144                     /* row pitch bytes (64 halves + 8 pad) */
#define ASTG_B (2 * 64 * ATPB)       /* K tile + V tile per stage = 18432 B */
#define A_SMEM_BYTES (3 * ASTG_B)    /* 55296 B */

__global__ __launch_bounds__(256, 2) void attn_fp16(
    const __half* __restrict__ qkv, __half* __restrict__ out) {
    extern __shared__ char smc[];
    uint32_t smemBase = smem_u32(smc);

    int t = threadIdx.x;
    int w = t >> 5, lane = t & 31;
    int g = lane >> 2, c = lane & 3;
    int bh = blockIdx.y;
    int n  = bh >> 4;
    int h  = bh & 15;
    int q0 = blockIdx.x * 128;
    int hcol = h * HDIM;

    // K (normal ldmatrix, B-operand role) lane offset
    const uint32_t kOff = (uint32_t)(((lane & 7) + ((lane >> 4) * 8)) * ATPB
                                     + ((lane >> 3) & 1) * 16);
    // V (trans ldmatrix) lane offset: rows = key, 16B col chunks = d
    const uint32_t vOff = (uint32_t)(64 * ATPB)
                        + (uint32_t)((((lane >> 3) & 1) * 8 + (lane & 7)) * ATPB
                                     + (lane >> 4) * 16);

    // ---- Q fragments (registers, packed half2, scaled by 1/64 exactly) ----
    uint32_t qf[4][4];
    {
        int r0 = q0 + w * 16 + g;
        const __half* qp0 = qkv + ((size_t)(r0 * NB + n)) * (3 * EMB) + hcol;
        const __half* qp1 = qkv + ((size_t)((r0 + 8) * NB + n)) * (3 * EMB) + hcol;
        __half2 qsc = __half2half2(__float2half_rn(1.0f / 64.0f));
        #pragma unroll
        for (int kk = 0; kk < 4; kk++) {
            __half2 h0 = __hmul2(*(const __half2*)(qp0 + kk * 16 + 2 * c), qsc);
            __half2 h1 = __hmul2(*(const __half2*)(qp1 + kk * 16 + 2 * c), qsc);
            __half2 h2 = __hmul2(*(const __half2*)(qp0 + kk * 16 + 8 + 2 * c), qsc);
            __half2 h3 = __hmul2(*(const __half2*)(qp1 + kk * 16 + 8 + 2 * c), qsc);
            qf[kk][0] = *(uint32_t*)&h0; qf[kk][1] = *(uint32_t*)&h1;
            qf[kk][2] = *(uint32_t*)&h2; qf[kk][3] = *(uint32_t*)&h3;
        }
    }

    float o_[8][4];
    #pragma unroll
    for (int j = 0; j < 8; j++)
        #pragma unroll
        for (int q = 0; q < 4; q++) o_[j][q] = 0.f;
    float m0 = -1e30f, m1 = -1e30f, l0 = 0.f, l1 = 0.f;

    auto load_kv = [&](int s, int k0) {
        uint32_t base = smemBase + (uint32_t)(s * ASTG_B);
        #pragma unroll
        for (int i = 0; i < 2; i++) {
            int idx = t + i * 256;               // 0..511
            int r = idx >> 3, cc = idx & 7;
            const __half* src = qkv + ((size_t)((k0 + r) * NB + n)) * (3 * EMB) + hcol + cc * 8;
            cp16(base + (uint32_t)(r * ATPB + cc * 16), src + EMB);                 // K
            cp16(base + (uint32_t)(64 * ATPB + r * ATPB + cc * 16), src + 2 * EMB); // V
        }
    };

    const int KT = L_SEQ / 64;
    load_kv(0, 0);  CP_COMMIT();
    load_kv(1, 64); CP_COMMIT();

    for (int kt = 0; kt < KT; kt++) {
        asm volatile("cp.async.wait_group 1;" ::: "memory");
        __syncthreads();
        if (kt + 2 < KT) load_kv((kt + 2) % 3, (kt + 2) * 64);
        CP_COMMIT();

        uint32_t stBase = smemBase + (uint32_t)((kt % 3) * ASTG_B);
        uint32_t ksA = stBase + kOff;
        uint32_t vsA = stBase + vOff;

        // ---- scores: S[16q x 64k] ----
        float s[8][4];
        #pragma unroll
        for (int j = 0; j < 8; j++)
            #pragma unroll
            for (int q = 0; q < 4; q++) s[j][q] = 0.f;
        #pragma unroll
        for (int kk = 0; kk < 4; kk++) {
            #pragma unroll
            for (int jp = 0; jp < 4; jp++) {
                uint32_t bf[4];
                ldsm4(bf, ksA + (uint32_t)(jp * 16 * ATPB) + (uint32_t)(kk * 32));
                mma_fp16(s[2 * jp],     qf[kk], &bf[0]);
                mma_fp16(s[2 * jp + 1], qf[kk], &bf[2]);
            }
        }

        // ---- online softmax (registers + quad shfl) ----
        float mx0 = s[0][0], mx1 = s[0][2];
        #pragma unroll
        for (int j = 0; j < 8; j++) {
            mx0 = fmaxf(mx0, fmaxf(s[j][0], s[j][1]));
            mx1 = fmaxf(mx1, fmaxf(s[j][2], s[j][3]));
        }
        mx0 = fmaxf(mx0, __shfl_xor_sync(0xffffffffu, mx0, 1));
        mx0 = fmaxf(mx0, __shfl_xor_sync(0xffffffffu, mx0, 2));
        mx1 = fmaxf(mx1, __shfl_xor_sync(0xffffffffu, mx1, 1));
        mx1 = fmaxf(mx1, __shfl_xor_sync(0xffffffffu, mx1, 2));
        float nm0 = fmaxf(m0, mx0), nm1 = fmaxf(m1, mx1);
        float corr0 = fexp(m0 - nm0), corr1 = fexp(m1 - nm1);
        m0 = nm0; m1 = nm1;
        float sum0 = 0.f, sum1 = 0.f;
        #pragma unroll
        for (int j = 0; j < 8; j++) {
            s[j][0] = fexp(s[j][0] - m0);
            s[j][1] = fexp(s[j][1] - m0);
            s[j][2] = fexp(s[j][2] - m1);
            s[j][3] = fexp(s[j][3] - m1);
            sum0 += s[j][0] + s[j][1];
            sum1 += s[j][2] + s[j][3];
        }
        sum0 += __shfl_xor_sync(0xffffffffu, sum0, 1);
        sum0 += __shfl_xor_sync(0xffffffffu, sum0, 2);
        sum1 += __shfl_xor_sync(0xffffffffu, sum1, 1);
        sum1 += __shfl_xor_sync(0xffffffffu, sum1, 2);
        l0 = l0 * corr0 + sum0;
        l1 = l1 * corr1 + sum1;
        #pragma unroll
        for (int j = 0; j < 8; j++) {
            o_[j][0] *= corr0; o_[j][1] *= corr0;
            o_[j][2] *= corr1; o_[j][3] *= corr1;
        }

        // ---- PV: pack P into a-frags; trans-ldmatrix V as B-frags ----
        #pragma unroll
        for (int u = 0; u < 4; u++) {            // keys 16u..16u+15
            uint32_t pa[4];
            pa[0] = packh2(s[2 * u][0],     s[2 * u][1]);
            pa[1] = packh2(s[2 * u][2],     s[2 * u][3]);
            pa[2] = packh2(s[2 * u + 1][0], s[2 * u + 1][1]);
            pa[3] = packh2(s[2 * u + 1][2], s[2 * u + 1][3]);
            #pragma unroll
            for (int jp2 = 0; jp2 < 2; jp2++) {  // d 32jp2 .. +31 in two ldsm
                #pragma unroll
                for (int hh2 = 0; hh2 < 2; hh2++) {
                    uint32_t bf[4];
                    ldsm4t(bf, vsA + (uint32_t)(u * 16 * ATPB)
                                 + (uint32_t)((jp2 * 2 + hh2) * 32));
                    int j = (jp2 * 2 + hh2) * 2;
                    mma_fp16(o_[j],     pa, &bf[0]);
                    mma_fp16(o_[j + 1], pa, &bf[2]);
                }
            }
        }
    }

    // ---- write output (fp16, feeds out-proj GEMM) ----
    float inv0 = 1.0f / l0, inv1 = 1.0f / l1;
    int r0 = q0 + w * 16 + g;
    __half* out0 = out + ((size_t)(r0 * NB + n)) * EMB + hcol;
    __half* out1 = out + ((size_t)((r0 + 8) * NB + n)) * EMB + hcol;
    #pragma unroll
    for (int j = 0; j < 8; j++) {
        int col = 8 * j + 2 * c;
        *(uint32_t*)(out0 + col) = packh2(o_[j][0] * inv0, o_[j][1] * inv0);
        *(uint32_t*)(out1 + col) = packh2(o_[j][2] * inv1, o_[j][3] * inv1);
    }
}

// ---------------- driver --------------------------------------------------------
extern "C" void kernel_launch(void* const* d_in, const int* in_sizes, int n_in,
                              void* d_out, int out_size) {
    const float* x         = (const float*)d_in[0];
    const float* ln1_w     = (const float*)d_in[1];
    const float* ln1_b     = (const float*)d_in[2];
    const float* in_proj_w = (const float*)d_in[3];
    const float* in_proj_b = (const float*)d_in[4];
    const float* out_w     = (const float*)d_in[5];
    const float* out_b     = (const float*)d_in[6];
    const float* ln2_w     = (const float*)d_in[7];
    const float* ln2_b     = (const float*)d_in[8];
    const float* fc_w      = (const float*)d_in[9];
    const float* fc_b      = (const float*)d_in[10];
    const float* proj_w    = (const float*)d_in[11];
    const float* proj_b    = (const float*)d_in[12];
    float* out = (float*)d_out;

    __half *yh, *qkvh, *oh, *hh, *wh;
    float *x1;
    cudaGetSymbolAddress((void**)&yh,   g_yh);
    cudaGetSymbolAddress((void**)&qkvh, g_qkvh);
    cudaGetSymbolAddress((void**)&oh,   g_oh);
    cudaGetSymbolAddress((void**)&x1,   g_x1);
    cudaGetSymbolAddress((void**)&hh,   g_hh);
    cudaGetSymbolAddress((void**)&wh,   g_wh);
    __half* wh_inproj = wh;
    __half* wh_out    = wh + (size_t)3 * MM;
    __half* wh_fc     = wh + (size_t)4 * MM;
    __half* wh_proj   = wh + (size_t)8 * MM;

    static bool attr_done = false;
    if (!attr_done) {
        cudaFuncSetAttribute(gemm_fp16<0, 0>, cudaFuncAttributeMaxDynamicSharedMemorySize, G_SMEM_BYTES);
        cudaFuncSetAttribute(gemm_fp16<0, 1>, cudaFuncAttributeMaxDynamicSharedMemorySize, G_SMEM_BYTES);
        cudaFuncSetAttribute(gemm_fp16<1, 1>, cudaFuncAttributeMaxDynamicSharedMemorySize, G_SMEM_BYTES);
        cudaFuncSetAttribute(attn_fp16, cudaFuncAttributeMaxDynamicSharedMemorySize, A_SMEM_BYTES);
        attr_done = true;
    }

    // 0. convert weights to fp16
    cvt_half<<<(3 * MM / 4 + 255) / 256, 256>>>(in_proj_w, wh_inproj, 3 * MM / 4);
    cvt_half<<<(MM / 4 + 255) / 256, 256>>>(out_w, wh_out, MM / 4);
    cvt_half<<<(4 * MM / 4 + 255) / 256, 256>>>(fc_w, wh_fc, MM);
    cvt_half<<<(4 * MM / 4 + 255) / 256, 256>>>(proj_w, wh_proj, MM);

    // 1. y = LN1(x) -> fp16
    ln_kernel<<<ROWS, 256>>>(x, ln1_w, ln1_b, yh);
    // 2. qkv = y @ in_proj_w^T + b -> fp16
    gemm_fp16<0, 1><<<dim3(3 * EMB / GBN, ROWS / GBM), 256, G_SMEM_BYTES>>>(
        yh, wh_inproj, in_proj_b, nullptr, qkvh, ROWS, 3 * EMB, EMB);
    // 3. o = attention(qkv) -> fp16
    attn_fp16<<<dim3(L_SEQ / 128, NB * NHEAD), 256, A_SMEM_BYTES>>>(qkvh, oh);
    // 4. x1 = x + o @ out_w^T + b  (fp32)
    gemm_fp16<0, 0><<<dim3(EMB / GBN, ROWS / GBM), 256, G_SMEM_BYTES>>>(
        oh, wh_out, out_b, x, x1, ROWS, EMB, EMB);
    // 5. y = LN2(x1) -> fp16
    ln_kernel<<<ROWS, 256>>>(x1, ln2_w, ln2_b, yh);
    // 6. h = GELU(y @ fc_w^T + b) -> fp16
    gemm_fp16<1, 1><<<dim3(FFN / GBN, ROWS / GBM), 256, G_SMEM_BYTES>>>(
        yh, wh_fc, fc_b, nullptr, hh, ROWS, FFN, EMB);
    // 7. out = x1 + h @ proj_w^T + b  (fp32)
    gemm_fp16<0, 0><<<dim3(EMB / GBN, ROWS / GBM), 256, G_SMEM_BYTES>>>(
        hh, wh_proj, proj_b, x1, out, ROWS, EMB, FFN);
}

// round 9
// speedup vs baseline: 9.9200x; 1.0333x over previous
#include <cuda_runtime.h>
#include <cuda_fp16.h>
#include <math.h>
#include <stdint.h>

#define L_SEQ 2048
#define NB    2
#define EMB   1024
#define NHEAD 16
#define HDIM  64
#define ROWS  (L_SEQ * NB)   /* 4096 */
#define FFN   (4 * EMB)      /* 4096 */
#define MM    (1024 * 1024)

// ---------------- scratch (no allocation; __device__ globals) -------------------
__device__ __half g_yh[(size_t)ROWS * EMB];
__device__ __half g_qkvh[(size_t)ROWS * 3 * EMB];
__device__ __half g_oh[(size_t)ROWS * EMB];
__device__ float  g_x1[(size_t)ROWS * EMB];
__device__ __half g_hh[(size_t)ROWS * FFN];
__device__ __half g_wh[(size_t)12 * MM];     // fp16 weights: inproj|out|fc|proj

// ---------------- helpers -------------------------------------------------------
__device__ __forceinline__ uint32_t smem_u32(const void* p) {
    uint32_t a;
    asm("{ .reg .u64 t; cvta.to.shared.u64 t, %1; cvt.u32.u64 %0, t; }" : "=r"(a) : "l"(p));
    return a;
}
__device__ __forceinline__ void cp16(uint32_t s, const void* g) {
    asm volatile("cp.async.cg.shared.global [%0], [%1], 16;" :: "r"(s), "l"(g) : "memory");
}
#define CP_COMMIT() asm volatile("cp.async.commit_group;" ::: "memory")

__device__ __forceinline__ void mma_fp16(float* d, const uint32_t* a, const uint32_t* b) {
    asm volatile(
        "mma.sync.aligned.m16n8k16.row.col.f32.f16.f16.f32 "
        "{%0,%1,%2,%3}, {%4,%5,%6,%7}, {%8,%9}, {%0,%1,%2,%3};"
        : "+f"(d[0]), "+f"(d[1]), "+f"(d[2]), "+f"(d[3])
        : "r"(a[0]), "r"(a[1]), "r"(a[2]), "r"(a[3]), "r"(b[0]), "r"(b[1]));
}
__device__ __forceinline__ void ldsm4(uint32_t* r, uint32_t addr) {
    asm volatile("ldmatrix.sync.aligned.m8n8.x4.shared.b16 {%0,%1,%2,%3}, [%4];"
                 : "=r"(r[0]), "=r"(r[1]), "=r"(r[2]), "=r"(r[3]) : "r"(addr));
}
__device__ __forceinline__ void ldsm4t(uint32_t* r, uint32_t addr) {
    asm volatile("ldmatrix.sync.aligned.m8n8.x4.trans.shared.b16 {%0,%1,%2,%3}, [%4];"
                 : "=r"(r[0]), "=r"(r[1]), "=r"(r[2]), "=r"(r[3]) : "r"(addr));
}
__device__ __forceinline__ uint32_t packh2(float a, float b) {
    __half2 h = __floats2half2_rn(a, b);
    return *(uint32_t*)&h;
}

// fast exp: FFMA-only, rel err ~1e-7
__device__ __forceinline__ float fexp(float x) {
    x = fmaxf(x, -80.0f);
    float t = x * 1.4426950408889634f;
    float r = t + 12582912.0f;
    float i = r - 12582912.0f;
    float f = t - i;
    float p = 1.3333558146428443e-3f;
    p = fmaf(p, f, 9.6181291076284772e-3f);
    p = fmaf(p, f, 5.5504108664821580e-2f);
    p = fmaf(p, f, 2.4022650695910072e-1f);
    p = fmaf(p, f, 6.9314718055994531e-1f);
    p = fmaf(p, f, 1.0f);
    return p * __int_as_float(((int)i + 127) << 23);
}

// ---------------- fp32 -> fp16 conversion (weights), 2 float4/thread ------------
__global__ void cvt_half(const float* __restrict__ src, __half* __restrict__ dst, int n4) {
    int i = (blockIdx.x * blockDim.x + threadIdx.x) * 2;
    if (i + 1 < n4 + 1) {
        float4 v0 = ((const float4*)src)[i];
        float4 v1 = ((const float4*)src)[i + 1];
        uint2 u0 = {packh2(v0.x, v0.y), packh2(v0.z, v0.w)};
        uint2 u1 = {packh2(v1.x, v1.y), packh2(v1.z, v1.w)};
        ((uint2*)dst)[i] = u0;
        ((uint2*)dst)[i + 1] = u1;
    }
}

// ---------------- LayerNorm: fp32 in -> fp16 out --------------------------------
__global__ void ln_kernel(const float* __restrict__ x,
                          const float* __restrict__ w,
                          const float* __restrict__ b,
                          __half* __restrict__ y) {
    int row = blockIdx.x;
    int t = threadIdx.x;
    const float4 v = ((const float4*)(x + (size_t)row * EMB))[t];
    float s  = v.x + v.y + v.z + v.w;
    float sq = v.x * v.x + v.y * v.y + v.z * v.z + v.w * v.w;
    #pragma unroll
    for (int o = 16; o; o >>= 1) {
        s  += __shfl_xor_sync(0xffffffffu, s, o);
        sq += __shfl_xor_sync(0xffffffffu, sq, o);
    }
    __shared__ float ss[8], ssq[8];
    int wid = t >> 5, lid = t & 31;
    if (lid == 0) { ss[wid] = s; ssq[wid] = sq; }
    __syncthreads();
    if (t == 0) {
        float a = 0.f, c = 0.f;
        #pragma unroll
        for (int i = 0; i < 8; i++) { a += ss[i]; c += ssq[i]; }
        ss[0] = a; ssq[0] = c;
    }
    __syncthreads();
    float mu  = ss[0] * (1.0f / EMB);
    float var = ssq[0] * (1.0f / EMB) - mu * mu;
    float rs  = rsqrtf(var + 1e-5f);
    const float4 wv = ((const float4*)w)[t];
    const float4 bv = ((const float4*)b)[t];
    uint2 o;
    o.x = packh2((v.x - mu) * rs * wv.x + bv.x, (v.y - mu) * rs * wv.y + bv.y);
    o.y = packh2((v.z - mu) * rs * wv.z + bv.z, (v.w - mu) * rs * wv.w + bv.w);
    ((uint2*)(y + (size_t)row * EMB))[t] = o;
}

// ---------------- fp16 mma GEMM: C[M,Nn] = A[M,K]*B[Nn,K]^T ---------------------
// Block 128x128, BK=32 halves, 8 warps 2x4 (warp tile 64x32), 4-stage cp.async.
#define GBM 128
#define GBN 128
#define GBK 32
#define GP  40                                  /* pitch in halves (80B) */
#define STAGE_H (2 * GBM * GP)
#define NSTAGE 4
#define G_SMEM_BYTES (NSTAGE * STAGE_H * 2)     /* 81920 B */

template <int ACT, int OHALF>
__global__ __launch_bounds__(256, 2)
void gemm_fp16(const __half* __restrict__ A, const __half* __restrict__ B,
               const float* __restrict__ bias, const float* __restrict__ res,
               void* __restrict__ Cout, int M, int Nn, int K) {
    extern __shared__ char smc[];
    uint32_t smemBase = smem_u32(smc);
    int t = threadIdx.x;
    int w = t >> 5, lane = t & 31;
    int g = lane >> 2, c = lane & 3;
    int wm = w & 1, wn = w >> 1;
    int m0 = blockIdx.y * GBM;
    int n0 = blockIdx.x * GBN;
    int KT = K / GBK;

    const __half* Ab = A + (size_t)m0 * K;
    const __half* Bb = B + (size_t)n0 * K;

    const uint32_t aOff = (uint32_t)((wm * 64 + (lane & 15)) * 80 + (lane >> 4) * 16);
    const uint32_t bOff = (uint32_t)(GBM * GP * 2)
                        + (uint32_t)((wn * 32 + (lane & 7) + ((lane >> 4) * 8)) * 80
                                     + ((lane >> 3) & 1) * 16);

    float d[4][4][4];
    #pragma unroll
    for (int i = 0; i < 4; i++)
        #pragma unroll
        for (int j = 0; j < 4; j++)
            #pragma unroll
            for (int q = 0; q < 4; q++) d[i][j][q] = 0.f;

    auto load_stage = [&](int s, int k0) {
        uint32_t aS = smemBase + (uint32_t)(s * STAGE_H * 2);
        uint32_t bS = aS + GBM * GP * 2;
        #pragma unroll
        for (int i = 0; i < 2; i++) {
            int ch = t + i * 256;
            int row = ch >> 2, cc = ch & 3;
            cp16(aS + (uint32_t)(row * 80 + cc * 16), Ab + (size_t)row * K + k0 + cc * 8);
            cp16(bS + (uint32_t)(row * 80 + cc * 16), Bb + (size_t)row * K + k0 + cc * 8);
        }
    };

    load_stage(0, 0);       CP_COMMIT();
    load_stage(1, GBK);     CP_COMMIT();
    load_stage(2, 2 * GBK); CP_COMMIT();

    for (int kt = 0; kt < KT; kt++) {
        asm volatile("cp.async.wait_group 2;" ::: "memory");
        __syncthreads();
        if (kt + 3 < KT) load_stage((kt + 3) & 3, (kt + 3) * GBK);
        CP_COMMIT();

        uint32_t stBase = smemBase + (uint32_t)((kt & 3) * STAGE_H * 2);
        uint32_t aAddr = stBase + aOff;
        uint32_t bAddr = stBase + bOff;

        // batch all B frags for both k16 chunks up front (MLP right after barrier)
        uint32_t b[2][2][4];
        #pragma unroll
        for (int kk = 0; kk < 2; kk++)
            #pragma unroll
            for (int jp = 0; jp < 2; jp++)
                ldsm4(b[kk][jp], bAddr + (uint32_t)(jp * 16 * 80) + (uint32_t)(kk * 32));

        #pragma unroll
        for (int kk = 0; kk < 2; kk++) {
            uint32_t kb = (uint32_t)(kk * 32);
            uint32_t a[4][4];
            #pragma unroll
            for (int i = 0; i < 4; i++)
                ldsm4(a[i], aAddr + (uint32_t)(i * 16 * 80) + kb);
            #pragma unroll
            for (int i = 0; i < 4; i++)
                #pragma unroll
                for (int j = 0; j < 4; j++)
                    mma_fp16(d[i][j], a[i], &b[kk][j >> 1][(j & 1) * 2]);
        }
    }

    // ---- epilogue ----
    #pragma unroll
    for (int i = 0; i < 4; i++) {
        int row0 = m0 + wm * 64 + i * 16 + g;
        #pragma unroll
        for (int j = 0; j < 4; j++) {
            int col = n0 + wn * 32 + j * 8 + 2 * c;
            float2 bv = *(const float2*)(bias + col);
            float v0 = d[i][j][0] + bv.x;
            float v1 = d[i][j][1] + bv.y;
            float v2 = d[i][j][2] + bv.x;
            float v3 = d[i][j][3] + bv.y;
            if (ACT == 1) {
                v0 = 0.5f * v0 * (1.0f + erff(v0 * 0.70710678118f));
                v1 = 0.5f * v1 * (1.0f + erff(v1 * 0.70710678118f));
                v2 = 0.5f * v2 * (1.0f + erff(v2 * 0.70710678118f));
                v3 = 0.5f * v3 * (1.0f + erff(v3 * 0.70710678118f));
            }
            if (OHALF) {
                __half* Ch = (__half*)Cout;
                *(uint32_t*)(Ch + (size_t)row0 * Nn + col)       = packh2(v0, v1);
                *(uint32_t*)(Ch + (size_t)(row0 + 8) * Nn + col) = packh2(v2, v3);
            } else {
                if (res != nullptr) {
                    float2 r0 = *(const float2*)(res + (size_t)row0 * Nn + col);
                    float2 r1 = *(const float2*)(res + (size_t)(row0 + 8) * Nn + col);
                    v0 += r0.x; v1 += r0.y; v2 += r1.x; v3 += r1.y;
                }
                float* Cf = (float*)Cout;
                float2 o0 = {v0, v1}, o1 = {v2, v3};
                *(float2*)(Cf + (size_t)row0 * Nn + col) = o0;
                *(float2*)(Cf + (size_t)(row0 + 8) * Nn + col) = o1;
            }
        }
    }
}

// ---------------- Flash attention, fp16, 3-stage K/V pipeline, trans-ldmatrix V --
#define ATPB 144                     /* row pitch bytes (64 halves + 8 pad) */
#define ASTG_B (2 * 64 * ATPB)       /* K tile + V tile per stage = 18432 B */
#define A_SMEM_BYTES (3 * ASTG_B)    /* 55296 B */

__global__ __launch_bounds__(256, 2) void attn_fp16(
    const __half* __restrict__ qkv, __half* __restrict__ out) {
    extern __shared__ char smc[];
    uint32_t smemBase = smem_u32(smc);

    int t = threadIdx.x;
    int w = t >> 5, lane = t & 31;
    int g = lane >> 2, c = lane & 3;
    int bh = blockIdx.y;
    int n  = bh >> 4;
    int h  = bh & 15;
    int q0 = blockIdx.x * 128;
    int hcol = h * HDIM;

    const uint32_t kOff = (uint32_t)(((lane & 7) + ((lane >> 4) * 8)) * ATPB
                                     + ((lane >> 3) & 1) * 16);
    const uint32_t vOff = (uint32_t)(64 * ATPB)
                        + (uint32_t)((((lane >> 3) & 1) * 8 + (lane & 7)) * ATPB
                                     + (lane >> 4) * 16);

    // ---- Q fragments (registers, packed half2, scaled by 1/64 exactly) ----
    uint32_t qf[4][4];
    {
        int r0 = q0 + w * 16 + g;
        const __half* qp0 = qkv + ((size_t)(r0 * NB + n)) * (3 * EMB) + hcol;
        const __half* qp1 = qkv + ((size_t)((r0 + 8) * NB + n)) * (3 * EMB) + hcol;
        __half2 qsc = __half2half2(__float2half_rn(1.0f / 64.0f));
        #pragma unroll
        for (int kk = 0; kk < 4; kk++) {
            __half2 h0 = __hmul2(*(const __half2*)(qp0 + kk * 16 + 2 * c), qsc);
            __half2 h1 = __hmul2(*(const __half2*)(qp1 + kk * 16 + 2 * c), qsc);
            __half2 h2 = __hmul2(*(const __half2*)(qp0 + kk * 16 + 8 + 2 * c), qsc);
            __half2 h3 = __hmul2(*(const __half2*)(qp1 + kk * 16 + 8 + 2 * c), qsc);
            qf[kk][0] = *(uint32_t*)&h0; qf[kk][1] = *(uint32_t*)&h1;
            qf[kk][2] = *(uint32_t*)&h2; qf[kk][3] = *(uint32_t*)&h3;
        }
    }

    float o_[8][4];
    #pragma unroll
    for (int j = 0; j < 8; j++)
        #pragma unroll
        for (int q = 0; q < 4; q++) o_[j][q] = 0.f;
    float m0 = -1e30f, m1 = -1e30f, l0 = 0.f, l1 = 0.f;

    auto load_kv = [&](int s, int k0) {
        uint32_t base = smemBase + (uint32_t)(s * ASTG_B);
        #pragma unroll
        for (int i = 0; i < 2; i++) {
            int idx = t + i * 256;
            int r = idx >> 3, cc = idx & 7;
            const __half* src = qkv + ((size_t)((k0 + r) * NB + n)) * (3 * EMB) + hcol + cc * 8;
            cp16(base + (uint32_t)(r * ATPB + cc * 16), src + EMB);                 // K
            cp16(base + (uint32_t)(64 * ATPB + r * ATPB + cc * 16), src + 2 * EMB); // V
        }
    };

    const int KT = L_SEQ / 64;
    load_kv(0, 0);  CP_COMMIT();
    load_kv(1, 64); CP_COMMIT();

    for (int kt = 0; kt < KT; kt++) {
        asm volatile("cp.async.wait_group 1;" ::: "memory");
        __syncthreads();
        if (kt + 2 < KT) load_kv((kt + 2) % 3, (kt + 2) * 64);
        CP_COMMIT();

        uint32_t stBase = smemBase + (uint32_t)((kt % 3) * ASTG_B);
        uint32_t ksA = stBase + kOff;
        uint32_t vsA = stBase + vOff;

        // ---- scores: S[16q x 64k] ----
        float s[8][4];
        #pragma unroll
        for (int j = 0; j < 8; j++)
            #pragma unroll
            for (int q = 0; q < 4; q++) s[j][q] = 0.f;
        #pragma unroll
        for (int kk = 0; kk < 4; kk++) {
            #pragma unroll
            for (int jp = 0; jp < 4; jp++) {
                uint32_t bf[4];
                ldsm4(bf, ksA + (uint32_t)(jp * 16 * ATPB) + (uint32_t)(kk * 32));
                mma_fp16(s[2 * jp],     qf[kk], &bf[0]);
                mma_fp16(s[2 * jp + 1], qf[kk], &bf[2]);
            }
        }

        // ---- online softmax (registers + quad shfl) ----
        float mx0 = s[0][0], mx1 = s[0][2];
        #pragma unroll
        for (int j = 0; j < 8; j++) {
            mx0 = fmaxf(mx0, fmaxf(s[j][0], s[j][1]));
            mx1 = fmaxf(mx1, fmaxf(s[j][2], s[j][3]));
        }
        mx0 = fmaxf(mx0, __shfl_xor_sync(0xffffffffu, mx0, 1));
        mx0 = fmaxf(mx0, __shfl_xor_sync(0xffffffffu, mx0, 2));
        mx1 = fmaxf(mx1, __shfl_xor_sync(0xffffffffu, mx1, 1));
        mx1 = fmaxf(mx1, __shfl_xor_sync(0xffffffffu, mx1, 2));
        float nm0 = fmaxf(m0, mx0), nm1 = fmaxf(m1, mx1);
        float corr0 = fexp(m0 - nm0), corr1 = fexp(m1 - nm1);
        m0 = nm0; m1 = nm1;
        float sum0 = 0.f, sum1 = 0.f;
        #pragma unroll
        for (int j = 0; j < 8; j++) {
            s[j][0] = fexp(s[j][0] - m0);
            s[j][1] = fexp(s[j][1] - m0);
            s[j][2] = fexp(s[j][2] - m1);
            s[j][3] = fexp(s[j][3] - m1);
            sum0 += s[j][0] + s[j][1];
            sum1 += s[j][2] + s[j][3];
        }
        sum0 += __shfl_xor_sync(0xffffffffu, sum0, 1);
        sum0 += __shfl_xor_sync(0xffffffffu, sum0, 2);
        sum1 += __shfl_xor_sync(0xffffffffu, sum1, 1);
        sum1 += __shfl_xor_sync(0xffffffffu, sum1, 2);
        l0 = l0 * corr0 + sum0;
        l1 = l1 * corr1 + sum1;
        #pragma unroll
        for (int j = 0; j < 8; j++) {
            o_[j][0] *= corr0; o_[j][1] *= corr0;
            o_[j][2] *= corr1; o_[j][3] *= corr1;
        }

        // ---- PV: pack P into a-frags; trans-ldmatrix V as B-frags ----
        #pragma unroll
        for (int u = 0; u < 4; u++) {
            uint32_t pa[4];
            pa[0] = packh2(s[2 * u][0],     s[2 * u][1]);
            pa[1] = packh2(s[2 * u][2],     s[2 * u][3]);
            pa[2] = packh2(s[2 * u + 1][0], s[2 * u + 1][1]);
            pa[3] = packh2(s[2 * u + 1][2], s[2 * u + 1][3]);
            #pragma unroll
            for (int jp2 = 0; jp2 < 2; jp2++) {
                #pragma unroll
                for (int hh2 = 0; hh2 < 2; hh2++) {
                    uint32_t bf[4];
                    ldsm4t(bf, vsA + (uint32_t)(u * 16 * ATPB)
                                 + (uint32_t)((jp2 * 2 + hh2) * 32));
                    int j = (jp2 * 2 + hh2) * 2;
                    mma_fp16(o_[j],     pa, &bf[0]);
                    mma_fp16(o_[j + 1], pa, &bf[2]);
                }
            }
        }
    }

    // ---- write output (fp16, feeds out-proj GEMM) ----
    float inv0 = 1.0f / l0, inv1 = 1.0f / l1;
    int r0 = q0 + w * 16 + g;
    __half* out0 = out + ((size_t)(r0 * NB + n)) * EMB + hcol;
    __half* out1 = out + ((size_t)((r0 + 8) * NB + n)) * EMB + hcol;
    #pragma unroll
    for (int j = 0; j < 8; j++) {
        int col = 8 * j + 2 * c;
        *(uint32_t*)(out0 + col) = packh2(o_[j][0] * inv0, o_[j][1] * inv0);
        *(uint32_t*)(out1 + col) = packh2(o_[j][2] * inv1, o_[j][3] * inv1);
    }
}

// ---------------- driver --------------------------------------------------------
extern "C" void kernel_launch(void* const* d_in, const int* in_sizes, int n_in,
                              void* d_out, int out_size) {
    const float* x         = (const float*)d_in[0];
    const float* ln1_w     = (const float*)d_in[1];
    const float* ln1_b     = (const float*)d_in[2];
    const float* in_proj_w = (const float*)d_in[3];
    const float* in_proj_b = (const float*)d_in[4];
    const float* out_w     = (const float*)d_in[5];
    const float* out_b     = (const float*)d_in[6];
    const float* ln2_w     = (const float*)d_in[7];
    const float* ln2_b     = (const float*)d_in[8];
    const float* fc_w      = (const float*)d_in[9];
    const float* fc_b      = (const float*)d_in[10];
    const float* proj_w    = (const float*)d_in[11];
    const float* proj_b    = (const float*)d_in[12];
    float* out = (float*)d_out;

    __half *yh, *qkvh, *oh, *hh, *wh;
    float *x1;
    cudaGetSymbolAddress((void**)&yh,   g_yh);
    cudaGetSymbolAddress((void**)&qkvh, g_qkvh);
    cudaGetSymbolAddress((void**)&oh,   g_oh);
    cudaGetSymbolAddress((void**)&x1,   g_x1);
    cudaGetSymbolAddress((void**)&hh,   g_hh);
    cudaGetSymbolAddress((void**)&wh,   g_wh);
    __half* wh_inproj = wh;
    __half* wh_out    = wh + (size_t)3 * MM;
    __half* wh_fc     = wh + (size_t)4 * MM;
    __half* wh_proj   = wh + (size_t)8 * MM;

    static cudaStream_t sW = nullptr;
    static cudaEvent_t evFork = nullptr, evW = nullptr;
    static bool attr_done = false;
    if (!attr_done) {
        cudaFuncSetAttribute(gemm_fp16<0, 0>, cudaFuncAttributeMaxDynamicSharedMemorySize, G_SMEM_BYTES);
        cudaFuncSetAttribute(gemm_fp16<0, 1>, cudaFuncAttributeMaxDynamicSharedMemorySize, G_SMEM_BYTES);
        cudaFuncSetAttribute(gemm_fp16<1, 1>, cudaFuncAttributeMaxDynamicSharedMemorySize, G_SMEM_BYTES);
        cudaFuncSetAttribute(attn_fp16, cudaFuncAttributeMaxDynamicSharedMemorySize, A_SMEM_BYTES);
        cudaStreamCreateWithFlags(&sW, cudaStreamNonBlocking);
        cudaEventCreateWithFlags(&evFork, cudaEventDisableTiming);
        cudaEventCreateWithFlags(&evW, cudaEventDisableTiming);
        attr_done = true;
    }

    // 0a. in-proj weights on main stream (needed by kernel 2)
    cvt_half<<<(3 * MM / 8 + 255) / 256, 256>>>(in_proj_w, wh_inproj, 3 * MM / 4);
    // 0b. fork: out/fc/proj weight conversion runs concurrently with LN1/QKV/attn
    cudaEventRecord(evFork, 0);
    cudaStreamWaitEvent(sW, evFork, 0);
    cvt_half<<<(MM / 8 + 255) / 256, 256, 0, sW>>>(out_w, wh_out, MM / 4);
    cvt_half<<<(MM / 2 + 255) / 256, 256, 0, sW>>>(fc_w, wh_fc, MM);
    cvt_half<<<(MM / 2 + 255) / 256, 256, 0, sW>>>(proj_w, wh_proj, MM);
    cudaEventRecord(evW, sW);

    // 1. y = LN1(x) -> fp16
    ln_kernel<<<ROWS, 256>>>(x, ln1_w, ln1_b, yh);
    // 2. qkv = y @ in_proj_w^T + b -> fp16
    gemm_fp16<0, 1><<<dim3(3 * EMB / GBN, ROWS / GBM), 256, G_SMEM_BYTES>>>(
        yh, wh_inproj, in_proj_b, nullptr, qkvh, ROWS, 3 * EMB, EMB);
    // 3. o = attention(qkv) -> fp16
    attn_fp16<<<dim3(L_SEQ / 128, NB * NHEAD), 256, A_SMEM_BYTES>>>(qkvh, oh);
    // join: remaining weights must be converted before kernel 4/6/7
    cudaStreamWaitEvent(0, evW, 0);
    // 4. x1 = x + o @ out_w^T + b  (fp32)
    gemm_fp16<0, 0><<<dim3(EMB / GBN, ROWS / GBM), 256, G_SMEM_BYTES>>>(
        oh, wh_out, out_b, x, x1, ROWS, EMB, EMB);
    // 5. y = LN2(x1) -> fp16
    ln_kernel<<<ROWS, 256>>>(x1, ln2_w, ln2_b, yh);
    // 6. h = GELU(y @ fc_w^T + b) -> fp16
    gemm_fp16<1, 1><<<dim3(FFN / GBN, ROWS / GBM), 256, G_SMEM_BYTES>>>(
        yh, wh_fc, fc_b, nullptr, hh, ROWS, FFN, EMB);
    // 7. out = x1 + h @ proj_w^T + b  (fp32)
    gemm_fp16<0, 0><<<dim3(EMB / GBN, ROWS / GBM), 256, G_SMEM_BYTES>>>(
        hh, wh_proj, proj_b, x1, out, ROWS, EMB, FFN);
}